// round 6
// baseline (speedup 1.0000x reference)
#include <cuda_runtime.h>
#include <cuda_bf16.h>
#include <cstdint>
#include <cstddef>

static constexpr int BATCH = 32;
static constexpr int NVERT = 5023;
static constexpr int SP    = 9;

// ---------------------------------------------------------------------------
// Helpers (sm_100 base target: mma.sync + ldmatrix + cp.async only)
// ---------------------------------------------------------------------------
__device__ __forceinline__ uint32_t smem_u32(const void* p) {
    uint32_t a;
    asm("{ .reg .u64 t; cvta.to.shared.u64 t, %1; cvt.u32.u64 %0, t; }" : "=r"(a) : "l"(p));
    return a;
}
__device__ __forceinline__ void cp16(uint32_t dst, const void* src, int srcbytes) {
    asm volatile("cp.async.ca.shared.global [%0], [%1], 16, %2;"
                 :: "r"(dst), "l"(src), "r"(srcbytes));
}
__device__ __forceinline__ void cp_commit() {
    asm volatile("cp.async.commit_group;" ::: "memory");
}
__device__ __forceinline__ void cp_wait1() {
    asm volatile("cp.async.wait_group 1;" ::: "memory");
}
__device__ __forceinline__ void ldm4(uint32_t addr, uint32_t* r) {
    asm volatile("ldmatrix.sync.aligned.m8n8.x4.shared.b16 {%0,%1,%2,%3}, [%4];"
                 : "=r"(r[0]), "=r"(r[1]), "=r"(r[2]), "=r"(r[3]) : "r"(addr));
}
__device__ __forceinline__ void mma16816(float* d, const uint32_t* a, const uint32_t* b) {
    asm volatile("mma.sync.aligned.m16n8k16.row.col.f32.bf16.bf16.f32 "
                 "{%0,%1,%2,%3}, {%4,%5,%6,%7}, {%8,%9}, {%0,%1,%2,%3};"
                 : "+f"(d[0]), "+f"(d[1]), "+f"(d[2]), "+f"(d[3])
                 : "r"(a[0]), "r"(a[1]), "r"(a[2]), "r"(a[3]), "r"(b[0]), "r"(b[1]));
}
// SW64 swizzle for 64-byte rows (8 rows x 64B atom = 512B)
__device__ __forceinline__ uint32_t swz64(uint32_t off) { return off ^ ((off >> 3) & 0x30); }

// ---------------------------------------------------------------------------
// Device global scratch
// ---------------------------------------------------------------------------
__device__ __nv_bfloat16 g_h1hi[(size_t)BATCH * NVERT * 32];
__device__ __nv_bfloat16 g_h1lo[(size_t)BATCH * NVERT * 32];
__device__ __nv_bfloat16 g_h2hi[(size_t)BATCH * NVERT * 64];
__device__ __nv_bfloat16 g_h2lo[(size_t)BATCH * NVERT * 64];
__device__ __nv_bfloat16 g_h3hi[(size_t)BATCH * NVERT * 128];
__device__ __nv_bfloat16 g_h3lo[(size_t)BATCH * NVERT * 128];
__device__ __nv_bfloat16 g_h4hi[(size_t)BATCH * NVERT * 128];
__device__ __nv_bfloat16 g_h4lo[(size_t)BATCH * NVERT * 128];

__device__ float g_wt0[27 * 32];
__device__ __nv_bfloat16 g_w1hi[64 * 320],   g_w1lo[64 * 320];
__device__ __nv_bfloat16 g_w2hi[128 * 576],  g_w2lo[128 * 576];
__device__ __nv_bfloat16 g_w3hi[128 * 1152], g_w3lo[128 * 1152];
__device__ __nv_bfloat16 g_wlhi[256 * 128],  g_wllo[256 * 128];

// ---------------------------------------------------------------------------
// Fused weight-prep kernel
// ---------------------------------------------------------------------------
__global__ void prep_weights(const float* W0, float* wt0,
                             const float* W1, __nv_bfloat16* w1hi, __nv_bfloat16* w1lo,
                             const float* W2, __nv_bfloat16* w2hi, __nv_bfloat16* w2lo,
                             const float* W3, __nv_bfloat16* w3hi, __nv_bfloat16* w3lo,
                             const float* Wl, __nv_bfloat16* wlhi, __nv_bfloat16* wllo) {
    int t = blockIdx.x * blockDim.x + threadIdx.x;
    if (t < 864) {
        int k = t / 32, o = t - k * 32;
        wt0[t] = W0[o * 27 + k];
        return;
    }
    t -= 864;
    const float* W; __nv_bfloat16* hi; __nv_bfloat16* lo; int K, KPAD;
    if (t < 64 * 320)                       { W = W1; hi = w1hi; lo = w1lo; K = 288;  KPAD = 320;  }
    else if ((t -= 64 * 320)  < 128 * 576)  { W = W2; hi = w2hi; lo = w2lo; K = 576;  KPAD = 576;  }
    else if ((t -= 128 * 576) < 128 * 1152) { W = W3; hi = w3hi; lo = w3lo; K = 1152; KPAD = 1152; }
    else if ((t -= 128 * 1152) < 256 * 128) { W = Wl; hi = wlhi; lo = wllo; K = 128;  KPAD = 128;  }
    else return;
    int o = t / KPAD, k = t - o * KPAD;
    float w = (k < K) ? W[o * K + k] : 0.f;
    __nv_bfloat16 h = __float2bfloat16(w);
    hi[t] = h;
    lo[t] = __float2bfloat16(w - __bfloat162float(h));
}

// ---------------------------------------------------------------------------
// Layer 0 (SIMT fp32, tiny): 3 -> 32, emits hi/lo bf16 planes
// ---------------------------------------------------------------------------
__global__ void __launch_bounds__(128)
layer0_kernel(const float* __restrict__ x,
              const int*   __restrict__ sidx_g,
              const float* __restrict__ Wt,
              const float* __restrict__ bias,
              __nv_bfloat16* __restrict__ hout_hi,
              __nv_bfloat16* __restrict__ hout_lo) {
    constexpr int IN_C = 3, OUT_C = 32, KC = 27, ROWS = 128, TM = 8, TN = 4;
    constexpr int TX = OUT_C / TN;
    constexpr int NT = 128;
    constexpr int AS = KC + 1;

    extern __shared__ __align__(1024) char dsm[];
    float* Asm = (float*)dsm;
    float* Wsm = Asm + ROWS * AS;
    int*   sidx = (int*)(Wsm + KC * OUT_C);

    const int tid = threadIdx.x;
    const int tx = tid % TX, ty = tid / TX;
    const int v0 = blockIdx.x * 4;

    if (tid < 36) {
        int vt = tid / SP, s = tid - vt * SP;
        int v = v0 + vt; if (v >= NVERT) v = NVERT - 1;
        sidx[tid] = sidx_g[v * SP + s];
    }
    for (int t = tid; t < KC * OUT_C; t += NT) Wsm[t] = Wt[t];
    __syncthreads();
    for (int t = tid; t < ROWS * KC; t += NT) {
        int r = t / KC, kk = t - r * KC;
        int vt = r >> 5, b = r & 31;
        int s = kk / IN_C, c = kk - s * IN_C;
        int srow = sidx[vt * SP + s];
        Asm[r * AS + kk] = x[((size_t)b * NVERT + srow) * IN_C + c];
    }
    __syncthreads();

    float acc[TM][TN];
#pragma unroll
    for (int i = 0; i < TM; ++i)
#pragma unroll
        for (int j = 0; j < TN; ++j) acc[i][j] = 0.f;

#pragma unroll
    for (int k = 0; k < KC; ++k) {
        float a[TM];
#pragma unroll
        for (int i = 0; i < TM; ++i) a[i] = Asm[(ty * TM + i) * AS + k];
        float4 wv = *(const float4*)(Wsm + k * OUT_C + tx * TN);
        float w[TN] = {wv.x, wv.y, wv.z, wv.w};
#pragma unroll
        for (int i = 0; i < TM; ++i)
#pragma unroll
            for (int j = 0; j < TN; ++j) acc[i][j] += a[i] * w[j];
    }

#pragma unroll
    for (int i = 0; i < TM; ++i) {
        int r = ty * TM + i;
        int vt = r >> 5, b = r & 31;
        int v = v0 + vt;
        if (v < NVERT) {
            size_t off = ((size_t)b * NVERT + v) * OUT_C + tx * TN;
#pragma unroll
            for (int j = 0; j < TN; ++j) {
                float y = acc[i][j] + __ldg(&bias[tx * TN + j]);
                __nv_bfloat16 h = __float2bfloat16(y);
                hout_hi[off + j] = h;
                hout_lo[off + j] = __float2bfloat16(y - __bfloat162float(h));
            }
        }
    }
}

// ---------------------------------------------------------------------------
// HMMA bf16-split layer, 512 threads, KC=32, 3-stage cp.async pipeline
// (single __syncthreads per chunk). Block tile MROWS x OUT_C; warp grid
// WRG x WCG (16 warps). 3 MMA passes per k16: AhiBhi + AhiBlo + AloBhi.
// ---------------------------------------------------------------------------
template<int IN_C, int OUT_C, int KREAL, int KPAD, int MV, int WRG, int WCG,
         bool GATHER, bool FINAL>
__global__ void __launch_bounds__(512, 1)
mma_layer(const __nv_bfloat16* __restrict__ hin_hi,
          const __nv_bfloat16* __restrict__ hin_lo,
          const int*           __restrict__ sidx_g,
          const __nv_bfloat16* __restrict__ whi,
          const __nv_bfloat16* __restrict__ wlo,
          const float*         __restrict__ bias,
          __nv_bfloat16*       __restrict__ hout_hi,
          __nv_bfloat16*       __restrict__ hout_lo,
          float*               __restrict__ fout) {
    constexpr int NT    = 512;
    constexpr int MROWS = MV * 32;
    constexpr int NCH   = KPAD / 32;
    constexpr int ATB   = MROWS * 64;       // bytes per A plane-buffer (64B rows)
    constexpr int BTB   = OUT_C * 64;       // bytes per B plane-buffer
    constexpr int SM_A  = 2048;
    constexpr int SM_B  = SM_A + 6 * ATB;   // 3 stages x 2 planes
    constexpr int WARP_R = MROWS / WRG;
    constexpr int WARP_C = OUT_C / WCG;
    constexpr int RS = WARP_R / 16;
    constexpr int NO = WARP_C / 8;
    constexpr int TOT_A = MROWS * 4 * 2;    // 16B tasks (4 units/row, 2 planes)
    constexpr int TOT_B = OUT_C * 4 * 2;

    extern __shared__ __align__(1024) char dsm[];
    const uint32_t sbase = smem_u32(dsm);
    int*   sidx = (int*)dsm;                // MV*9 ints (<= 72)
    float* bsm  = (float*)(dsm + 512);      // OUT_C floats

    const int tid  = threadIdx.x;
    const int wid  = tid >> 5;
    const int lane = tid & 31;
    const int v0   = blockIdx.x * MV;

    const int wr = wid % WRG, wc = wid / WRG;
    const int warp_r0 = wr * WARP_R;
    const int warp_c0 = wc * WARP_C;

    if (GATHER && tid < MV * SP) {
        int vt = tid / SP, s = tid - vt * SP;
        int v = v0 + vt; if (v >= NVERT) v = NVERT - 1;
        sidx[tid] = sidx_g[v * SP + s];
    }
    for (int t = tid; t < OUT_C; t += NT) bsm[t] = bias[t];
    __syncthreads();

    // ---- chunk loader into pipeline stage st ----
    auto load_chunk = [&](int ch, int st) {
#pragma unroll
        for (int t = tid; t < TOT_A; t += NT) {
            int plane = t >= MROWS * 4;
            int rg = plane ? t - MROWS * 4 : t;
            int r = rg >> 2, g = rg & 3;
            int vt = r >> 5, b = r & 31;
            int kg = ch * 32 + g * 8;
            int kgc = kg < KREAL ? kg : 0;
            int s = GATHER ? kgc / IN_C : 0;
            int c = GATHER ? kgc - s * IN_C : kgc;
            int v = v0 + vt; if (v >= NVERT) v = NVERT - 1;
            int srow = GATHER ? sidx[vt * SP + s] : v;
            const __nv_bfloat16* src = (plane ? hin_lo : hin_hi)
                + ((size_t)b * NVERT + srow) * IN_C + c;
            uint32_t dst = sbase + SM_A + (uint32_t)(st * 2 + plane) * ATB
                         + swz64((uint32_t)(r * 64 + g * 16));
            cp16(dst, src, kg < KREAL ? 16 : 0);
        }
#pragma unroll
        for (int t = tid; t < TOT_B; t += NT) {
            int plane = t >= OUT_C * 4;
            int rg = plane ? t - OUT_C * 4 : t;
            int n = rg >> 2, g = rg & 3;
            int kg = ch * 32 + g * 8;
            const __nv_bfloat16* src = (plane ? wlo : whi) + (size_t)n * KPAD + kg;
            uint32_t dst = sbase + SM_B + (uint32_t)(st * 2 + plane) * BTB
                         + swz64((uint32_t)(n * 64 + g * 16));
            cp16(dst, src, 16);
        }
        cp_commit();
    };

    float acc[RS][NO][4];
#pragma unroll
    for (int i = 0; i < RS; ++i)
#pragma unroll
        for (int j = 0; j < NO; ++j)
#pragma unroll
            for (int q = 0; q < 4; ++q) acc[i][j][q] = 0.f;

    const int grp = lane >> 3, lr = lane & 7;

    load_chunk(0, 0);
    load_chunk(1, 1);

    int st = 0;           // stage of chunk ch
    for (int ch = 0; ch < NCH; ++ch) {
        cp_wait1();       // groups pending: {ch, ch+1} -> completes ch
        __syncthreads();  // chunk ch visible to all; all warps done with ch-1

        // prefetch ch+2 into the stage of ch-1 (freed by the barrier above)
        if (ch + 2 < NCH) load_chunk(ch + 2, (st + 2) % 3);
        else              cp_commit();

        const uint32_t Ahi = sbase + SM_A + (uint32_t)(st * 2 + 0) * ATB;
        const uint32_t Alo = sbase + SM_A + (uint32_t)(st * 2 + 1) * ATB;
        const uint32_t Bhi = sbase + SM_B + (uint32_t)(st * 2 + 0) * BTB;
        const uint32_t Blo = sbase + SM_B + (uint32_t)(st * 2 + 1) * BTB;

#pragma unroll
        for (int ks = 0; ks < 2; ++ks) {            // 2 k16 steps per chunk
            uint32_t bh[NO][2], bl_[NO][2];
#pragma unroll
            for (int p16 = 0; p16 < NO / 2; ++p16) {
                int n  = warp_c0 + p16 * 16 + (grp >> 1) * 8 + lr;
                int c16 = ks * 2 + (grp & 1);
                uint32_t off = swz64((uint32_t)(n * 64 + c16 * 16));
                uint32_t m[4];
                ldm4(Bhi + off, m);
                bh[2 * p16][0] = m[0]; bh[2 * p16][1] = m[1];
                bh[2 * p16 + 1][0] = m[2]; bh[2 * p16 + 1][1] = m[3];
                ldm4(Blo + off, m);
                bl_[2 * p16][0] = m[0]; bl_[2 * p16][1] = m[1];
                bl_[2 * p16 + 1][0] = m[2]; bl_[2 * p16 + 1][1] = m[3];
            }
#pragma unroll
            for (int sub = 0; sub < RS; ++sub) {
                int row = warp_r0 + sub * 16 + (grp & 1) * 8 + lr;
                int c16 = ks * 2 + (grp >> 1);
                uint32_t off = swz64((uint32_t)(row * 64 + c16 * 16));
                uint32_t ah[4], al[4];
                ldm4(Ahi + off, ah);
                ldm4(Alo + off, al);
#pragma unroll
                for (int oct = 0; oct < NO; ++oct) {
                    mma16816(acc[sub][oct], ah, bh[oct]);
                    mma16816(acc[sub][oct], ah, bl_[oct]);
                    mma16816(acc[sub][oct], al, bh[oct]);
                }
            }
        }
        st = (st + 1) % 3;
    }

    // ---- epilogue: bias + (re-split | f32) stores straight from D frags ----
    const int tq = lane >> 2, tr = lane & 3;
#pragma unroll
    for (int sub = 0; sub < RS; ++sub) {
#pragma unroll
        for (int half = 0; half < 2; ++half) {
            int r = warp_r0 + sub * 16 + half * 8 + tq;
            int vt = r >> 5, b = r & 31;
            int v = v0 + vt;
            if (v >= NVERT) continue;
#pragma unroll
            for (int oct = 0; oct < NO; ++oct) {
                int col = warp_c0 + oct * 8 + tr * 2;
                float y0 = acc[sub][oct][2 * half]     + bsm[col];
                float y1 = acc[sub][oct][2 * half + 1] + bsm[col + 1];
                size_t base = ((size_t)b * NVERT + v) * OUT_C + col;
                if (FINAL) {
                    *(float2*)(fout + base) = make_float2(y0, y1);
                } else {
                    __nv_bfloat16 h0 = __float2bfloat16(y0);
                    __nv_bfloat16 h1 = __float2bfloat16(y1);
                    __nv_bfloat162 hp; hp.x = h0; hp.y = h1;
                    __nv_bfloat162 lp;
                    lp.x = __float2bfloat16(y0 - __bfloat162float(h0));
                    lp.y = __float2bfloat16(y1 - __bfloat162float(h1));
                    *(uint32_t*)(hout_hi + base) = *reinterpret_cast<uint32_t*>(&hp);
                    *(uint32_t*)(hout_lo + base) = *reinterpret_cast<uint32_t*>(&lp);
                }
            }
        }
    }
}

// ---------------------------------------------------------------------------
// Host
// ---------------------------------------------------------------------------
extern "C" void kernel_launch(void* const* d_in, const int* in_sizes, int n_in,
                              void* d_out, int out_size) {
    const float* x  = (const float*)d_in[0];
    const int*   sp = (const int*)  d_in[1];
    const float* W0 = (const float*)d_in[2];
    const float* b0 = (const float*)d_in[3];
    const float* W1 = (const float*)d_in[4];
    const float* b1 = (const float*)d_in[5];
    const float* W2 = (const float*)d_in[6];
    const float* b2 = (const float*)d_in[7];
    const float* W3 = (const float*)d_in[8];
    const float* b3 = (const float*)d_in[9];
    const float* Wl = (const float*)d_in[10];
    const float* bl = (const float*)d_in[11];
    float* out = (float*)d_out;

    __nv_bfloat16 *h1hi, *h1lo, *h2hi, *h2lo, *h3hi, *h3lo, *h4hi, *h4lo;
    __nv_bfloat16 *w1hi, *w1lo, *w2hi, *w2lo, *w3hi, *w3lo, *wlhi, *wllo;
    float *wt0;
    cudaGetSymbolAddress((void**)&h1hi, g_h1hi);  cudaGetSymbolAddress((void**)&h1lo, g_h1lo);
    cudaGetSymbolAddress((void**)&h2hi, g_h2hi);  cudaGetSymbolAddress((void**)&h2lo, g_h2lo);
    cudaGetSymbolAddress((void**)&h3hi, g_h3hi);  cudaGetSymbolAddress((void**)&h3lo, g_h3lo);
    cudaGetSymbolAddress((void**)&h4hi, g_h4hi);  cudaGetSymbolAddress((void**)&h4lo, g_h4lo);
    cudaGetSymbolAddress((void**)&w1hi, g_w1hi);  cudaGetSymbolAddress((void**)&w1lo, g_w1lo);
    cudaGetSymbolAddress((void**)&w2hi, g_w2hi);  cudaGetSymbolAddress((void**)&w2lo, g_w2lo);
    cudaGetSymbolAddress((void**)&w3hi, g_w3hi);  cudaGetSymbolAddress((void**)&w3lo, g_w3lo);
    cudaGetSymbolAddress((void**)&wlhi, g_wlhi);  cudaGetSymbolAddress((void**)&wllo, g_wllo);
    cudaGetSymbolAddress((void**)&wt0,  g_wt0);

    // ---- fused weight prep (1 launch) ----
    {
        const int total = 864 + 64 * 320 + 128 * 576 + 128 * 1152 + 256 * 128;
        prep_weights<<<(total + 255) / 256, 256>>>(W0, wt0, W1, w1hi, w1lo,
                                                   W2, w2hi, w2lo, W3, w3hi, w3lo,
                                                   Wl, wlhi, wllo);
    }

    const int* sp0 = sp + 0 * NVERT * SP;
    const int* sp1 = sp + 1 * NVERT * SP;
    const int* sp2 = sp + 2 * NVERT * SP;
    const int* sp3 = sp + 3 * NVERT * SP;

    const int grid4 = (NVERT + 3) / 4;   // 1256 (layer0, final)
    const int grid8 = (NVERT + 7) / 8;   // 628  (MMA layers, MV=8)

    // ---- Layer 0 (SIMT) ----
    {
        constexpr int smb = (128 * 28 + 27 * 32) * 4 + 64 * 4;
        layer0_kernel<<<grid4, 128, smb>>>(x, sp0, wt0, b0, h1hi, h1lo);
    }
    // ---- Layer 1: 32 -> 64, K=288 (pad 320), M=256 ----
    {
        auto k = mma_layer<32, 64, 288, 320, 8, 4, 4, true, false>;
        constexpr int smb = 2048 + 6 * (256 * 64) + 6 * (64 * 64);   // 124928
        cudaFuncSetAttribute((const void*)k, cudaFuncAttributeMaxDynamicSharedMemorySize, smb);
        k<<<grid8, 512, smb>>>(h1hi, h1lo, sp1, w1hi, w1lo, b1, h2hi, h2lo, nullptr);
    }
    // ---- Layer 2: 64 -> 128, K=576, M=256 ----
    {
        auto k = mma_layer<64, 128, 576, 576, 8, 4, 4, true, false>;
        constexpr int smb = 2048 + 6 * (256 * 64) + 6 * (128 * 64);  // 149504
        cudaFuncSetAttribute((const void*)k, cudaFuncAttributeMaxDynamicSharedMemorySize, smb);
        k<<<grid8, 512, smb>>>(h2hi, h2lo, sp2, w2hi, w2lo, b2, h3hi, h3lo, nullptr);
    }
    // ---- Layer 3: 128 -> 128, K=1152, M=256 ----
    {
        auto k = mma_layer<128, 128, 1152, 1152, 8, 4, 4, true, false>;
        constexpr int smb = 2048 + 6 * (256 * 64) + 6 * (128 * 64); // 149504
        cudaFuncSetAttribute((const void*)k, cudaFuncAttributeMaxDynamicSharedMemorySize, smb);
        k<<<grid8, 512, smb>>>(h3hi, h3lo, sp3, w3hi, w3lo, b3, h4hi, h4lo, nullptr);
    }
    // ---- Final: 128 -> 256, no gather, M=128 ----
    {
        auto k = mma_layer<128, 256, 128, 128, 4, 2, 8, false, true>;
        constexpr int smb = 2048 + 6 * (128 * 64) + 6 * (256 * 64); // 149504
        cudaFuncSetAttribute((const void*)k, cudaFuncAttributeMaxDynamicSharedMemorySize, smb);
        k<<<grid4, 512, smb>>>(h4hi, h4lo, nullptr, wlhi, wllo, bl, nullptr, nullptr, out);
    }
}

// round 8
// speedup vs baseline: 1.1018x; 1.1018x over previous
#include <cuda_runtime.h>
#include <cuda_bf16.h>
#include <cstdint>
#include <cstddef>

static constexpr int BATCH = 32;
static constexpr int NVERT = 5023;
static constexpr int SP    = 9;

// ---------------------------------------------------------------------------
// Helpers (sm_100 base target: mma.sync + ldmatrix + cp.async only)
// ---------------------------------------------------------------------------
__device__ __forceinline__ uint32_t smem_u32(const void* p) {
    uint32_t a;
    asm("{ .reg .u64 t; cvta.to.shared.u64 t, %1; cvt.u32.u64 %0, t; }" : "=r"(a) : "l"(p));
    return a;
}
__device__ __forceinline__ void cp16(uint32_t dst, const void* src, int srcbytes) {
    asm volatile("cp.async.ca.shared.global [%0], [%1], 16, %2;"
                 :: "r"(dst), "l"(src), "r"(srcbytes));
}
__device__ __forceinline__ void cp_commit() {
    asm volatile("cp.async.commit_group;" ::: "memory");
}
template<int N> __device__ __forceinline__ void cp_wait() {
    if constexpr (N == 0) asm volatile("cp.async.wait_group 0;" ::: "memory");
    else if constexpr (N == 1) asm volatile("cp.async.wait_group 1;" ::: "memory");
    else asm volatile("cp.async.wait_group 2;" ::: "memory");
}
__device__ __forceinline__ void ldm4(uint32_t addr, uint32_t* r) {
    asm volatile("ldmatrix.sync.aligned.m8n8.x4.shared.b16 {%0,%1,%2,%3}, [%4];"
                 : "=r"(r[0]), "=r"(r[1]), "=r"(r[2]), "=r"(r[3]) : "r"(addr));
}
__device__ __forceinline__ void mma16816(float* d, const uint32_t* a, const uint32_t* b) {
    asm volatile("mma.sync.aligned.m16n8k16.row.col.f32.bf16.bf16.f32 "
                 "{%0,%1,%2,%3}, {%4,%5,%6,%7}, {%8,%9}, {%0,%1,%2,%3};"
                 : "+f"(d[0]), "+f"(d[1]), "+f"(d[2]), "+f"(d[3])
                 : "r"(a[0]), "r"(a[1]), "r"(a[2]), "r"(a[3]), "r"(b[0]), "r"(b[1]));
}
// SW64 swizzle for 64-byte rows (8 rows x 64B atom = 512B)
__device__ __forceinline__ uint32_t swz64(uint32_t off) { return off ^ ((off >> 3) & 0x30); }

// ---------------------------------------------------------------------------
// Device global scratch
// ---------------------------------------------------------------------------
__device__ __nv_bfloat16 g_h1hi[(size_t)BATCH * NVERT * 32];
__device__ __nv_bfloat16 g_h1lo[(size_t)BATCH * NVERT * 32];
__device__ __nv_bfloat16 g_h2hi[(size_t)BATCH * NVERT * 64];
__device__ __nv_bfloat16 g_h2lo[(size_t)BATCH * NVERT * 64];
__device__ __nv_bfloat16 g_h3hi[(size_t)BATCH * NVERT * 128];
__device__ __nv_bfloat16 g_h3lo[(size_t)BATCH * NVERT * 128];
__device__ __nv_bfloat16 g_h4hi[(size_t)BATCH * NVERT * 128];
__device__ __nv_bfloat16 g_h4lo[(size_t)BATCH * NVERT * 128];

__device__ float g_wt0[27 * 32];
__device__ __nv_bfloat16 g_w1hi[64 * 320],   g_w1lo[64 * 320];
__device__ __nv_bfloat16 g_w2hi[128 * 576],  g_w2lo[128 * 576];
__device__ __nv_bfloat16 g_w3hi[128 * 1152], g_w3lo[128 * 1152];
__device__ __nv_bfloat16 g_wlhi[256 * 128],  g_wllo[256 * 128];

// ---------------------------------------------------------------------------
// Fused weight-prep kernel
// ---------------------------------------------------------------------------
__global__ void prep_weights(const float* W0, float* wt0,
                             const float* W1, __nv_bfloat16* w1hi, __nv_bfloat16* w1lo,
                             const float* W2, __nv_bfloat16* w2hi, __nv_bfloat16* w2lo,
                             const float* W3, __nv_bfloat16* w3hi, __nv_bfloat16* w3lo,
                             const float* Wl, __nv_bfloat16* wlhi, __nv_bfloat16* wllo) {
    int t = blockIdx.x * blockDim.x + threadIdx.x;
    if (t < 864) {
        int k = t / 32, o = t - k * 32;
        wt0[t] = W0[o * 27 + k];
        return;
    }
    t -= 864;
    const float* W; __nv_bfloat16* hi; __nv_bfloat16* lo; int K, KPAD;
    if (t < 64 * 320)                       { W = W1; hi = w1hi; lo = w1lo; K = 288;  KPAD = 320;  }
    else if ((t -= 64 * 320)  < 128 * 576)  { W = W2; hi = w2hi; lo = w2lo; K = 576;  KPAD = 576;  }
    else if ((t -= 128 * 576) < 128 * 1152) { W = W3; hi = w3hi; lo = w3lo; K = 1152; KPAD = 1152; }
    else if ((t -= 128 * 1152) < 256 * 128) { W = Wl; hi = wlhi; lo = wllo; K = 128;  KPAD = 128;  }
    else return;
    int o = t / KPAD, k = t - o * KPAD;
    float w = (k < K) ? W[o * K + k] : 0.f;
    __nv_bfloat16 h = __float2bfloat16(w);
    hi[t] = h;
    lo[t] = __float2bfloat16(w - __bfloat162float(h));
}

// ---------------------------------------------------------------------------
// Layer 0 (SIMT fp32, tiny): 3 -> 32, emits hi/lo bf16 planes
// ---------------------------------------------------------------------------
__global__ void __launch_bounds__(128)
layer0_kernel(const float* __restrict__ x,
              const int*   __restrict__ sidx_g,
              const float* __restrict__ Wt,
              const float* __restrict__ bias,
              __nv_bfloat16* __restrict__ hout_hi,
              __nv_bfloat16* __restrict__ hout_lo) {
    constexpr int IN_C = 3, OUT_C = 32, KC = 27, ROWS = 128, TM = 8, TN = 4;
    constexpr int TX = OUT_C / TN;
    constexpr int NT = 128;
    constexpr int AS = KC + 1;

    extern __shared__ __align__(1024) char dsm[];
    float* Asm = (float*)dsm;
    float* Wsm = Asm + ROWS * AS;
    int*   sidx = (int*)(Wsm + KC * OUT_C);

    const int tid = threadIdx.x;
    const int tx = tid % TX, ty = tid / TX;
    const int v0 = blockIdx.x * 4;

    if (tid < 36) {
        int vt = tid / SP, s = tid - vt * SP;
        int v = v0 + vt; if (v >= NVERT) v = NVERT - 1;
        sidx[tid] = sidx_g[v * SP + s];
    }
    for (int t = tid; t < KC * OUT_C; t += NT) Wsm[t] = Wt[t];
    __syncthreads();
    for (int t = tid; t < ROWS * KC; t += NT) {
        int r = t / KC, kk = t - r * KC;
        int vt = r >> 5, b = r & 31;
        int s = kk / IN_C, c = kk - s * IN_C;
        int srow = sidx[vt * SP + s];
        Asm[r * AS + kk] = x[((size_t)b * NVERT + srow) * IN_C + c];
    }
    __syncthreads();

    float acc[TM][TN];
#pragma unroll
    for (int i = 0; i < TM; ++i)
#pragma unroll
        for (int j = 0; j < TN; ++j) acc[i][j] = 0.f;

#pragma unroll
    for (int k = 0; k < KC; ++k) {
        float a[TM];
#pragma unroll
        for (int i = 0; i < TM; ++i) a[i] = Asm[(ty * TM + i) * AS + k];
        float4 wv = *(const float4*)(Wsm + k * OUT_C + tx * TN);
        float w[TN] = {wv.x, wv.y, wv.z, wv.w};
#pragma unroll
        for (int i = 0; i < TM; ++i)
#pragma unroll
            for (int j = 0; j < TN; ++j) acc[i][j] += a[i] * w[j];
    }

#pragma unroll
    for (int i = 0; i < TM; ++i) {
        int r = ty * TM + i;
        int vt = r >> 5, b = r & 31;
        int v = v0 + vt;
        if (v < NVERT) {
            size_t off = ((size_t)b * NVERT + v) * OUT_C + tx * TN;
#pragma unroll
            for (int j = 0; j < TN; ++j) {
                float y = acc[i][j] + __ldg(&bias[tx * TN + j]);
                __nv_bfloat16 h = __float2bfloat16(y);
                hout_hi[off + j] = h;
                hout_lo[off + j] = __float2bfloat16(y - __bfloat162float(h));
            }
        }
    }
}

// ---------------------------------------------------------------------------
// HMMA bf16-split layer, 256 threads, KC=32, NSTAGE-deep cp.async pipeline
// with ONE __syncthreads per chunk. Block tile MROWS x OUT_C; warp grid
// WRG x WCG (8 warps). 3 MMA passes per k16: AhiBhi + AhiBlo + AloBhi.
// smem header: [0,256) sidx, [256,1280) bias (max 256 floats), [2048...) tiles.
// ---------------------------------------------------------------------------
template<int IN_C, int OUT_C, int KREAL, int KPAD, int MV, int WRG, int WCG,
         int NSTAGE, bool GATHER, bool FINAL>
__global__ void __launch_bounds__(256, 2)
mma_layer(const __nv_bfloat16* __restrict__ hin_hi,
          const __nv_bfloat16* __restrict__ hin_lo,
          const int*           __restrict__ sidx_g,
          const __nv_bfloat16* __restrict__ whi,
          const __nv_bfloat16* __restrict__ wlo,
          const float*         __restrict__ bias,
          __nv_bfloat16*       __restrict__ hout_hi,
          __nv_bfloat16*       __restrict__ hout_lo,
          float*               __restrict__ fout) {
    constexpr int NT    = 256;
    constexpr int MROWS = MV * 32;
    constexpr int NCH   = KPAD / 32;
    constexpr int ATB   = MROWS * 64;       // bytes per A plane-buffer (64B rows)
    constexpr int BTB   = OUT_C * 64;       // bytes per B plane-buffer
    constexpr int SM_A  = 2048;             // after sidx [0,256) + bias [256,1280)
    constexpr int SM_B  = SM_A + 2 * NSTAGE * ATB;
    constexpr int WARP_R = MROWS / WRG;
    constexpr int WARP_C = OUT_C / WCG;
    constexpr int RS = WARP_R / 16;
    constexpr int NO = WARP_C / 8;
    constexpr int TOT_A = MROWS * 4 * 2;    // 16B tasks (4 units/row, 2 planes)
    constexpr int TOT_B = OUT_C * 4 * 2;

    extern __shared__ __align__(1024) char dsm[];
    const uint32_t sbase = smem_u32(dsm);
    int*   sidx = (int*)dsm;                // MV*9 ints (<= 36) @ [0,256)
    float* bsm  = (float*)(dsm + 256);      // OUT_C floats (<=256) @ [256,1280)

    const int tid  = threadIdx.x;
    const int wid  = tid >> 5;
    const int lane = tid & 31;
    const int v0   = blockIdx.x * MV;

    const int wr = wid % WRG, wc = wid / WRG;
    const int warp_r0 = wr * WARP_R;
    const int warp_c0 = wc * WARP_C;

    if (GATHER && tid < MV * SP) {
        int vt = tid / SP, s = tid - vt * SP;
        int v = v0 + vt; if (v >= NVERT) v = NVERT - 1;
        sidx[tid] = sidx_g[v * SP + s];
    }
    for (int t = tid; t < OUT_C; t += NT) bsm[t] = bias[t];
    __syncthreads();

    // ---- chunk loader into pipeline stage st ----
    auto load_chunk = [&](int ch, int st) {
#pragma unroll
        for (int t = tid; t < TOT_A; t += NT) {
            int plane = t >= MROWS * 4;
            int rg = plane ? t - MROWS * 4 : t;
            int r = rg >> 2, g = rg & 3;
            int vt = r >> 5, b = r & 31;
            int kg = ch * 32 + g * 8;
            int kgc = kg < KREAL ? kg : 0;
            int s = GATHER ? kgc / IN_C : 0;
            int c = GATHER ? kgc - s * IN_C : kgc;
            int v = v0 + vt; if (v >= NVERT) v = NVERT - 1;
            int srow = GATHER ? sidx[vt * SP + s] : v;
            const __nv_bfloat16* src = (plane ? hin_lo : hin_hi)
                + ((size_t)b * NVERT + srow) * IN_C + c;
            uint32_t dst = sbase + SM_A + (uint32_t)(st * 2 + plane) * ATB
                         + swz64((uint32_t)(r * 64 + g * 16));
            cp16(dst, src, kg < KREAL ? 16 : 0);
        }
#pragma unroll
        for (int t = tid; t < TOT_B; t += NT) {
            int plane = t >= OUT_C * 4;
            int rg = plane ? t - OUT_C * 4 : t;
            int n = rg >> 2, g = rg & 3;
            int kg = ch * 32 + g * 8;
            const __nv_bfloat16* src = (plane ? wlo : whi) + (size_t)n * KPAD + kg;
            uint32_t dst = sbase + SM_B + (uint32_t)(st * 2 + plane) * BTB
                         + swz64((uint32_t)(n * 64 + g * 16));
            cp16(dst, src, 16);
        }
        cp_commit();
    };

    float acc[RS][NO][4];
#pragma unroll
    for (int i = 0; i < RS; ++i)
#pragma unroll
        for (int j = 0; j < NO; ++j)
#pragma unroll
            for (int q = 0; q < 4; ++q) acc[i][j][q] = 0.f;

    const int grp = lane >> 3, lr = lane & 7;

#pragma unroll
    for (int i = 0; i < NSTAGE - 1; ++i) load_chunk(i, i);

    for (int ch = 0; ch < NCH; ++ch) {
        const int st = ch % NSTAGE;
        cp_wait<NSTAGE - 2>();   // chunk ch complete
        __syncthreads();         // all warps done with the stage being refilled

        // prefetch ch+NSTAGE-1 into the stage freed by the barrier above
        if (ch + NSTAGE - 1 < NCH) load_chunk(ch + NSTAGE - 1, (ch + NSTAGE - 1) % NSTAGE);
        else                       cp_commit();   // keep group counts aligned

        const uint32_t Ahi = sbase + SM_A + (uint32_t)(st * 2 + 0) * ATB;
        const uint32_t Alo = sbase + SM_A + (uint32_t)(st * 2 + 1) * ATB;
        const uint32_t Bhi = sbase + SM_B + (uint32_t)(st * 2 + 0) * BTB;
        const uint32_t Blo = sbase + SM_B + (uint32_t)(st * 2 + 1) * BTB;

#pragma unroll
        for (int ks = 0; ks < 2; ++ks) {            // 2 k16 steps per chunk
            uint32_t bh[NO][2], bl_[NO][2];
#pragma unroll
            for (int p16 = 0; p16 < NO / 2; ++p16) {
                int n  = warp_c0 + p16 * 16 + (grp >> 1) * 8 + lr;
                int c16 = ks * 2 + (grp & 1);
                uint32_t off = swz64((uint32_t)(n * 64 + c16 * 16));
                uint32_t m[4];
                ldm4(Bhi + off, m);
                bh[2 * p16][0] = m[0]; bh[2 * p16][1] = m[1];
                bh[2 * p16 + 1][0] = m[2]; bh[2 * p16 + 1][1] = m[3];
                ldm4(Blo + off, m);
                bl_[2 * p16][0] = m[0]; bl_[2 * p16][1] = m[1];
                bl_[2 * p16 + 1][0] = m[2]; bl_[2 * p16 + 1][1] = m[3];
            }
#pragma unroll
            for (int sub = 0; sub < RS; ++sub) {
                int row = warp_r0 + sub * 16 + (grp & 1) * 8 + lr;
                int c16 = ks * 2 + (grp >> 1);
                uint32_t off = swz64((uint32_t)(row * 64 + c16 * 16));
                uint32_t ah[4], al[4];
                ldm4(Ahi + off, ah);
                ldm4(Alo + off, al);
#pragma unroll
                for (int oct = 0; oct < NO; ++oct) {
                    mma16816(acc[sub][oct], ah, bh[oct]);
                    mma16816(acc[sub][oct], ah, bl_[oct]);
                    mma16816(acc[sub][oct], al, bh[oct]);
                }
            }
        }
    }

    // ---- epilogue: bias + (re-split | f32) stores straight from D frags ----
    const int tq = lane >> 2, tr = lane & 3;
#pragma unroll
    for (int sub = 0; sub < RS; ++sub) {
#pragma unroll
        for (int half = 0; half < 2; ++half) {
            int r = warp_r0 + sub * 16 + half * 8 + tq;
            int vt = r >> 5, b = r & 31;
            int v = v0 + vt;
            if (v >= NVERT) continue;
#pragma unroll
            for (int oct = 0; oct < NO; ++oct) {
                int col = warp_c0 + oct * 8 + tr * 2;
                float y0 = acc[sub][oct][2 * half]     + bsm[col];
                float y1 = acc[sub][oct][2 * half + 1] + bsm[col + 1];
                size_t base = ((size_t)b * NVERT + v) * OUT_C + col;
                if (FINAL) {
                    *(float2*)(fout + base) = make_float2(y0, y1);
                } else {
                    __nv_bfloat16 h0 = __float2bfloat16(y0);
                    __nv_bfloat16 h1 = __float2bfloat16(y1);
                    __nv_bfloat162 hp; hp.x = h0; hp.y = h1;
                    __nv_bfloat162 lp;
                    lp.x = __float2bfloat16(y0 - __bfloat162float(h0));
                    lp.y = __float2bfloat16(y1 - __bfloat162float(h1));
                    *(uint32_t*)(hout_hi + base) = *reinterpret_cast<uint32_t*>(&hp);
                    *(uint32_t*)(hout_lo + base) = *reinterpret_cast<uint32_t*>(&lp);
                }
            }
        }
    }
}

// ---------------------------------------------------------------------------
// Host
// ---------------------------------------------------------------------------
extern "C" void kernel_launch(void* const* d_in, const int* in_sizes, int n_in,
                              void* d_out, int out_size) {
    const float* x  = (const float*)d_in[0];
    const int*   sp = (const int*)  d_in[1];
    const float* W0 = (const float*)d_in[2];
    const float* b0 = (const float*)d_in[3];
    const float* W1 = (const float*)d_in[4];
    const float* b1 = (const float*)d_in[5];
    const float* W2 = (const float*)d_in[6];
    const float* b2 = (const float*)d_in[7];
    const float* W3 = (const float*)d_in[8];
    const float* b3 = (const float*)d_in[9];
    const float* Wl = (const float*)d_in[10];
    const float* bl = (const float*)d_in[11];
    float* out = (float*)d_out;

    __nv_bfloat16 *h1hi, *h1lo, *h2hi, *h2lo, *h3hi, *h3lo, *h4hi, *h4lo;
    __nv_bfloat16 *w1hi, *w1lo, *w2hi, *w2lo, *w3hi, *w3lo, *wlhi, *wllo;
    float *wt0;
    cudaGetSymbolAddress((void**)&h1hi, g_h1hi);  cudaGetSymbolAddress((void**)&h1lo, g_h1lo);
    cudaGetSymbolAddress((void**)&h2hi, g_h2hi);  cudaGetSymbolAddress((void**)&h2lo, g_h2lo);
    cudaGetSymbolAddress((void**)&h3hi, g_h3hi);  cudaGetSymbolAddress((void**)&h3lo, g_h3lo);
    cudaGetSymbolAddress((void**)&h4hi, g_h4hi);  cudaGetSymbolAddress((void**)&h4lo, g_h4lo);
    cudaGetSymbolAddress((void**)&w1hi, g_w1hi);  cudaGetSymbolAddress((void**)&w1lo, g_w1lo);
    cudaGetSymbolAddress((void**)&w2hi, g_w2hi);  cudaGetSymbolAddress((void**)&w2lo, g_w2lo);
    cudaGetSymbolAddress((void**)&w3hi, g_w3hi);  cudaGetSymbolAddress((void**)&w3lo, g_w3lo);
    cudaGetSymbolAddress((void**)&wlhi, g_wlhi);  cudaGetSymbolAddress((void**)&wllo, g_wllo);
    cudaGetSymbolAddress((void**)&wt0,  g_wt0);

    // ---- fused weight prep (1 launch) ----
    {
        const int total = 864 + 64 * 320 + 128 * 576 + 128 * 1152 + 256 * 128;
        prep_weights<<<(total + 255) / 256, 256>>>(W0, wt0, W1, w1hi, w1lo,
                                                   W2, w2hi, w2lo, W3, w3hi, w3lo,
                                                   Wl, wlhi, wllo);
    }

    const int* sp0 = sp + 0 * NVERT * SP;
    const int* sp1 = sp + 1 * NVERT * SP;
    const int* sp2 = sp + 2 * NVERT * SP;
    const int* sp3 = sp + 3 * NVERT * SP;

    const int grid4 = (NVERT + 3) / 4;   // 1256
    const int grid2 = (NVERT + 1) / 2;   // 2512

    // ---- Layer 0 (SIMT) ----
    {
        constexpr int smb = (128 * 28 + 27 * 32) * 4 + 64 * 4;
        layer0_kernel<<<grid4, 128, smb>>>(x, sp0, wt0, b0, h1hi, h1lo);
    }
    // ---- Layer 1: 32 -> 64, K=288 (pad 320), M=128, 3-stage ----
    {
        auto k = mma_layer<32, 64, 288, 320, 4, 4, 2, 3, true, false>;
        constexpr int smb = 2048 + 6 * (128 * 64) + 6 * (64 * 64);   // 75776
        cudaFuncSetAttribute((const void*)k, cudaFuncAttributeMaxDynamicSharedMemorySize, smb);
        k<<<grid4, 256, smb>>>(h1hi, h1lo, sp1, w1hi, w1lo, b1, h2hi, h2lo, nullptr);
    }
    // ---- Layer 2: 64 -> 128, K=576, M=128, 3-stage ----
    {
        auto k = mma_layer<64, 128, 576, 576, 4, 2, 4, 3, true, false>;
        constexpr int smb = 2048 + 6 * (128 * 64) + 6 * (128 * 64);  // 100352
        cudaFuncSetAttribute((const void*)k, cudaFuncAttributeMaxDynamicSharedMemorySize, smb);
        k<<<grid4, 256, smb>>>(h2hi, h2lo, sp2, w2hi, w2lo, b2, h3hi, h3lo, nullptr);
    }
    // ---- Layer 3: 128 -> 128, K=1152, M=128, 3-stage ----
    {
        auto k = mma_layer<128, 128, 1152, 1152, 4, 2, 4, 3, true, false>;
        constexpr int smb = 2048 + 6 * (128 * 64) + 6 * (128 * 64);  // 100352
        cudaFuncSetAttribute((const void*)k, cudaFuncAttributeMaxDynamicSharedMemorySize, smb);
        k<<<grid4, 256, smb>>>(h3hi, h3lo, sp3, w3hi, w3lo, b3, h4hi, h4lo, nullptr);
    }
    // ---- Final: 128 -> 256, no gather, M=64, 2-stage ----
    {
        auto k = mma_layer<128, 256, 128, 128, 2, 2, 4, 2, false, true>;
        constexpr int smb = 2048 + 4 * (64 * 64) + 4 * (256 * 64);   // 83968
        cudaFuncSetAttribute((const void*)k, cudaFuncAttributeMaxDynamicSharedMemorySize, smb);
        k<<<grid2, 256, smb>>>(h4hi, h4lo, nullptr, wlhi, wllo, bl, nullptr, nullptr, out);
    }
}

// round 9
// speedup vs baseline: 1.3973x; 1.2682x over previous
#include <cuda_runtime.h>
#include <cuda_bf16.h>
#include <cstdint>
#include <cstddef>

static constexpr int BATCH = 32;
static constexpr int NVERT = 5023;
static constexpr int SP    = 9;

// ---------------------------------------------------------------------------
// Helpers (sm_100 base target: mma.sync + ldmatrix + cp.async only)
// ---------------------------------------------------------------------------
__device__ __forceinline__ uint32_t smem_u32(const void* p) {
    uint32_t a;
    asm("{ .reg .u64 t; cvta.to.shared.u64 t, %1; cvt.u32.u64 %0, t; }" : "=r"(a) : "l"(p));
    return a;
}
__device__ __forceinline__ void cp16(uint32_t dst, const void* src, int srcbytes) {
    asm volatile("cp.async.cg.shared.global [%0], [%1], 16, %2;"
                 :: "r"(dst), "l"(src), "r"(srcbytes));
}
__device__ __forceinline__ void cp_commit() {
    asm volatile("cp.async.commit_group;" ::: "memory");
}
template<int N> __device__ __forceinline__ void cp_wait() {
    if constexpr (N == 0) asm volatile("cp.async.wait_group 0;" ::: "memory");
    else if constexpr (N == 1) asm volatile("cp.async.wait_group 1;" ::: "memory");
    else asm volatile("cp.async.wait_group 2;" ::: "memory");
}
__device__ __forceinline__ void ldm4(uint32_t addr, uint32_t* r) {
    asm volatile("ldmatrix.sync.aligned.m8n8.x4.shared.b16 {%0,%1,%2,%3}, [%4];"
                 : "=r"(r[0]), "=r"(r[1]), "=r"(r[2]), "=r"(r[3]) : "r"(addr));
}
__device__ __forceinline__ void mma16816(float* d, const uint32_t* a, const uint32_t* b) {
    asm volatile("mma.sync.aligned.m16n8k16.row.col.f32.bf16.bf16.f32 "
                 "{%0,%1,%2,%3}, {%4,%5,%6,%7}, {%8,%9}, {%0,%1,%2,%3};"
                 : "+f"(d[0]), "+f"(d[1]), "+f"(d[2]), "+f"(d[3])
                 : "r"(a[0]), "r"(a[1]), "r"(a[2]), "r"(a[3]), "r"(b[0]), "r"(b[1]));
}
// SW64 swizzle for 64-byte rows (8 rows x 64B atom = 512B)
__device__ __forceinline__ uint32_t swz64(uint32_t off) { return off ^ ((off >> 3) & 0x30); }

// ---------------------------------------------------------------------------
// Device global scratch
// ---------------------------------------------------------------------------
__device__ __nv_bfloat16 g_h1hi[(size_t)BATCH * NVERT * 32];
__device__ __nv_bfloat16 g_h1lo[(size_t)BATCH * NVERT * 32];
__device__ __nv_bfloat16 g_h2hi[(size_t)BATCH * NVERT * 64];
__device__ __nv_bfloat16 g_h2lo[(size_t)BATCH * NVERT * 64];
__device__ __nv_bfloat16 g_h3hi[(size_t)BATCH * NVERT * 128];
__device__ __nv_bfloat16 g_h3lo[(size_t)BATCH * NVERT * 128];
__device__ __nv_bfloat16 g_h4hi[(size_t)BATCH * NVERT * 128];
__device__ __nv_bfloat16 g_h4lo[(size_t)BATCH * NVERT * 128];

__device__ float g_wt0[27 * 32];
__device__ __nv_bfloat16 g_w1hi[64 * 320],   g_w1lo[64 * 320];
__device__ __nv_bfloat16 g_w2hi[128 * 576],  g_w2lo[128 * 576];
__device__ __nv_bfloat16 g_w3hi[128 * 1152], g_w3lo[128 * 1152];
__device__ __nv_bfloat16 g_wlhi[256 * 128],  g_wllo[256 * 128];

// ---------------------------------------------------------------------------
// Fused weight-prep kernel
// ---------------------------------------------------------------------------
__global__ void prep_weights(const float* W0, float* wt0,
                             const float* W1, __nv_bfloat16* w1hi, __nv_bfloat16* w1lo,
                             const float* W2, __nv_bfloat16* w2hi, __nv_bfloat16* w2lo,
                             const float* W3, __nv_bfloat16* w3hi, __nv_bfloat16* w3lo,
                             const float* Wl, __nv_bfloat16* wlhi, __nv_bfloat16* wllo) {
    int t = blockIdx.x * blockDim.x + threadIdx.x;
    if (t < 864) {
        int k = t / 32, o = t - k * 32;
        wt0[t] = W0[o * 27 + k];
        return;
    }
    t -= 864;
    const float* W; __nv_bfloat16* hi; __nv_bfloat16* lo; int K, KPAD;
    if (t < 64 * 320)                       { W = W1; hi = w1hi; lo = w1lo; K = 288;  KPAD = 320;  }
    else if ((t -= 64 * 320)  < 128 * 576)  { W = W2; hi = w2hi; lo = w2lo; K = 576;  KPAD = 576;  }
    else if ((t -= 128 * 576) < 128 * 1152) { W = W3; hi = w3hi; lo = w3lo; K = 1152; KPAD = 1152; }
    else if ((t -= 128 * 1152) < 256 * 128) { W = Wl; hi = wlhi; lo = wllo; K = 128;  KPAD = 128;  }
    else return;
    int o = t / KPAD, k = t - o * KPAD;
    float w = (k < K) ? W[o * K + k] : 0.f;
    __nv_bfloat16 h = __float2bfloat16(w);
    hi[t] = h;
    lo[t] = __float2bfloat16(w - __bfloat162float(h));
}

// ---------------------------------------------------------------------------
// Layer 0 (SIMT fp32, tiny): 3 -> 32, emits hi/lo bf16 planes
// ---------------------------------------------------------------------------
__global__ void __launch_bounds__(128)
layer0_kernel(const float* __restrict__ x,
              const int*   __restrict__ sidx_g,
              const float* __restrict__ Wt,
              const float* __restrict__ bias,
              __nv_bfloat16* __restrict__ hout_hi,
              __nv_bfloat16* __restrict__ hout_lo) {
    constexpr int IN_C = 3, OUT_C = 32, KC = 27, ROWS = 128, TM = 8, TN = 4;
    constexpr int TX = OUT_C / TN;
    constexpr int NT = 128;
    constexpr int AS = KC + 1;

    extern __shared__ __align__(1024) char dsm[];
    float* Asm = (float*)dsm;
    float* Wsm = Asm + ROWS * AS;
    int*   sidx = (int*)(Wsm + KC * OUT_C);

    const int tid = threadIdx.x;
    const int tx = tid % TX, ty = tid / TX;
    const int v0 = blockIdx.x * 4;

    if (tid < 36) {
        int vt = tid / SP, s = tid - vt * SP;
        int v = v0 + vt; if (v >= NVERT) v = NVERT - 1;
        sidx[tid] = sidx_g[v * SP + s];
    }
    for (int t = tid; t < KC * OUT_C; t += NT) Wsm[t] = Wt[t];
    __syncthreads();
    for (int t = tid; t < ROWS * KC; t += NT) {
        int r = t / KC, kk = t - r * KC;
        int vt = r >> 5, b = r & 31;
        int s = kk / IN_C, c = kk - s * IN_C;
        int srow = sidx[vt * SP + s];
        Asm[r * AS + kk] = x[((size_t)b * NVERT + srow) * IN_C + c];
    }
    __syncthreads();

    float acc[TM][TN];
#pragma unroll
    for (int i = 0; i < TM; ++i)
#pragma unroll
        for (int j = 0; j < TN; ++j) acc[i][j] = 0.f;

#pragma unroll
    for (int k = 0; k < KC; ++k) {
        float a[TM];
#pragma unroll
        for (int i = 0; i < TM; ++i) a[i] = Asm[(ty * TM + i) * AS + k];
        float4 wv = *(const float4*)(Wsm + k * OUT_C + tx * TN);
        float w[TN] = {wv.x, wv.y, wv.z, wv.w};
#pragma unroll
        for (int i = 0; i < TM; ++i)
#pragma unroll
            for (int j = 0; j < TN; ++j) acc[i][j] += a[i] * w[j];
    }

#pragma unroll
    for (int i = 0; i < TM; ++i) {
        int r = ty * TM + i;
        int vt = r >> 5, b = r & 31;
        int v = v0 + vt;
        if (v < NVERT) {
            size_t off = ((size_t)b * NVERT + v) * OUT_C + tx * TN;
#pragma unroll
            for (int j = 0; j < TN; ++j) {
                float y = acc[i][j] + __ldg(&bias[tx * TN + j]);
                __nv_bfloat16 h = __float2bfloat16(y);
                hout_hi[off + j] = h;
                hout_lo[off + j] = __float2bfloat16(y - __bfloat162float(h));
            }
        }
    }
}

// ---------------------------------------------------------------------------
// HMMA bf16-split layer, 256 threads, KC=32, NSTAGE-deep cp.async pipeline.
// Prefetch of chunk ch+NSTAGE-1 is ISSUED BEFORE the wait on chunk ch so the
// address math + cp.async issue overlap with in-flight groups (R5 ordering).
// Two 8-warp barriers per chunk. 3 MMA passes per k16: AhiBhi+AhiBlo+AloBhi.
// smem header: [0,256) sidx, [256,1280) bias, [2048...) tiles.
// ---------------------------------------------------------------------------
template<int IN_C, int OUT_C, int KREAL, int KPAD, int MV, int WRG, int WCG,
         int NSTAGE, bool GATHER, bool FINAL>
__global__ void __launch_bounds__(256, 2)
mma_layer(const __nv_bfloat16* __restrict__ hin_hi,
          const __nv_bfloat16* __restrict__ hin_lo,
          const int*           __restrict__ sidx_g,
          const __nv_bfloat16* __restrict__ whi,
          const __nv_bfloat16* __restrict__ wlo,
          const float*         __restrict__ bias,
          __nv_bfloat16*       __restrict__ hout_hi,
          __nv_bfloat16*       __restrict__ hout_lo,
          float*               __restrict__ fout) {
    constexpr int NT    = 256;
    constexpr int MROWS = MV * 32;
    constexpr int NCH   = KPAD / 32;
    constexpr int ATB   = MROWS * 64;       // bytes per A plane-buffer (64B rows)
    constexpr int BTB   = OUT_C * 64;       // bytes per B plane-buffer
    constexpr int SM_A  = 2048;             // after sidx [0,256) + bias [256,1280)
    constexpr int SM_B  = SM_A + 2 * NSTAGE * ATB;
    constexpr int WARP_R = MROWS / WRG;
    constexpr int WARP_C = OUT_C / WCG;
    constexpr int RS = WARP_R / 16;
    constexpr int NO = WARP_C / 8;
    constexpr int TOT_A = MROWS * 4 * 2;    // 16B tasks (4 units/row, 2 planes)
    constexpr int TOT_B = OUT_C * 4 * 2;

    extern __shared__ __align__(1024) char dsm[];
    const uint32_t sbase = smem_u32(dsm);
    int*   sidx = (int*)dsm;                // MV*9 ints (<= 36) @ [0,256)
    float* bsm  = (float*)(dsm + 256);      // OUT_C floats (<=256) @ [256,1280)

    const int tid  = threadIdx.x;
    const int wid  = tid >> 5;
    const int lane = tid & 31;
    const int v0   = blockIdx.x * MV;

    const int wr = wid % WRG, wc = wid / WRG;
    const int warp_r0 = wr * WARP_R;
    const int warp_c0 = wc * WARP_C;

    if (GATHER && tid < MV * SP) {
        int vt = tid / SP, s = tid - vt * SP;
        int v = v0 + vt; if (v >= NVERT) v = NVERT - 1;
        sidx[tid] = sidx_g[v * SP + s];
    }
    for (int t = tid; t < OUT_C; t += NT) bsm[t] = bias[t];
    __syncthreads();

    // ---- chunk loader into pipeline stage st ----
    auto load_chunk = [&](int ch, int st) {
#pragma unroll
        for (int t = tid; t < TOT_A; t += NT) {
            int plane = t >= MROWS * 4;
            int rg = plane ? t - MROWS * 4 : t;
            int r = rg >> 2, g = rg & 3;
            int vt = r >> 5, b = r & 31;
            int kg = ch * 32 + g * 8;
            int kgc = kg < KREAL ? kg : 0;
            int s = GATHER ? kgc / IN_C : 0;
            int c = GATHER ? kgc - s * IN_C : kgc;
            int v = v0 + vt; if (v >= NVERT) v = NVERT - 1;
            int srow = GATHER ? sidx[vt * SP + s] : v;
            const __nv_bfloat16* src = (plane ? hin_lo : hin_hi)
                + ((size_t)b * NVERT + srow) * IN_C + c;
            uint32_t dst = sbase + SM_A + (uint32_t)(st * 2 + plane) * ATB
                         + swz64((uint32_t)(r * 64 + g * 16));
            cp16(dst, src, kg < KREAL ? 16 : 0);
        }
#pragma unroll
        for (int t = tid; t < TOT_B; t += NT) {
            int plane = t >= OUT_C * 4;
            int rg = plane ? t - OUT_C * 4 : t;
            int n = rg >> 2, g = rg & 3;
            int kg = ch * 32 + g * 8;
            const __nv_bfloat16* src = (plane ? wlo : whi) + (size_t)n * KPAD + kg;
            uint32_t dst = sbase + SM_B + (uint32_t)(st * 2 + plane) * BTB
                         + swz64((uint32_t)(n * 64 + g * 16));
            cp16(dst, src, 16);
        }
        cp_commit();
    };

    float acc[RS][NO][4];
#pragma unroll
    for (int i = 0; i < RS; ++i)
#pragma unroll
        for (int j = 0; j < NO; ++j)
#pragma unroll
            for (int q = 0; q < 4; ++q) acc[i][j][q] = 0.f;

    const int grp = lane >> 3, lr = lane & 7;

#pragma unroll
    for (int i = 0; i < NSTAGE - 1; ++i) load_chunk(i, i);

    for (int ch = 0; ch < NCH; ++ch) {
        const int st = ch % NSTAGE;

        // issue prefetch BEFORE waiting: overlaps addr math + cp issue with
        // the in-flight groups. Target stage was freed by the trailing
        // barrier of the previous iteration.
        if (ch + NSTAGE - 1 < NCH) load_chunk(ch + NSTAGE - 1, (ch + NSTAGE - 1) % NSTAGE);
        else                       cp_commit();   // keep group counts aligned

        cp_wait<NSTAGE - 1>();   // chunk ch complete (NSTAGE-1 newer pending)
        __syncthreads();         // chunk ch visible to all warps

        const uint32_t Ahi = sbase + SM_A + (uint32_t)(st * 2 + 0) * ATB;
        const uint32_t Alo = sbase + SM_A + (uint32_t)(st * 2 + 1) * ATB;
        const uint32_t Bhi = sbase + SM_B + (uint32_t)(st * 2 + 0) * BTB;
        const uint32_t Blo = sbase + SM_B + (uint32_t)(st * 2 + 1) * BTB;

#pragma unroll
        for (int ks = 0; ks < 2; ++ks) {            // 2 k16 steps per chunk
            uint32_t bh[NO][2], bl_[NO][2];
#pragma unroll
            for (int p16 = 0; p16 < NO / 2; ++p16) {
                int n  = warp_c0 + p16 * 16 + (grp >> 1) * 8 + lr;
                int c16 = ks * 2 + (grp & 1);
                uint32_t off = swz64((uint32_t)(n * 64 + c16 * 16));
                uint32_t m[4];
                ldm4(Bhi + off, m);
                bh[2 * p16][0] = m[0]; bh[2 * p16][1] = m[1];
                bh[2 * p16 + 1][0] = m[2]; bh[2 * p16 + 1][1] = m[3];
                ldm4(Blo + off, m);
                bl_[2 * p16][0] = m[0]; bl_[2 * p16][1] = m[1];
                bl_[2 * p16 + 1][0] = m[2]; bl_[2 * p16 + 1][1] = m[3];
            }
#pragma unroll
            for (int sub = 0; sub < RS; ++sub) {
                int row = warp_r0 + sub * 16 + (grp & 1) * 8 + lr;
                int c16 = ks * 2 + (grp >> 1);
                uint32_t off = swz64((uint32_t)(row * 64 + c16 * 16));
                uint32_t ah[4], al[4];
                ldm4(Ahi + off, ah);
                ldm4(Alo + off, al);
#pragma unroll
                for (int oct = 0; oct < NO; ++oct) {
                    mma16816(acc[sub][oct], ah, bh[oct]);
                    mma16816(acc[sub][oct], ah, bl_[oct]);
                    mma16816(acc[sub][oct], al, bh[oct]);
                }
            }
        }
        __syncthreads();         // all warps done with stage st before refill
    }

    // ---- epilogue: bias + (re-split | f32) stores straight from D frags ----
    const int tq = lane >> 2, tr = lane & 3;
#pragma unroll
    for (int sub = 0; sub < RS; ++sub) {
#pragma unroll
        for (int half = 0; half < 2; ++half) {
            int r = warp_r0 + sub * 16 + half * 8 + tq;
            int vt = r >> 5, b = r & 31;
            int v = v0 + vt;
            if (v >= NVERT) continue;
#pragma unroll
            for (int oct = 0; oct < NO; ++oct) {
                int col = warp_c0 + oct * 8 + tr * 2;
                float y0 = acc[sub][oct][2 * half]     + bsm[col];
                float y1 = acc[sub][oct][2 * half + 1] + bsm[col + 1];
                size_t base = ((size_t)b * NVERT + v) * OUT_C + col;
                if (FINAL) {
                    *(float2*)(fout + base) = make_float2(y0, y1);
                } else {
                    __nv_bfloat16 h0 = __float2bfloat16(y0);
                    __nv_bfloat16 h1 = __float2bfloat16(y1);
                    __nv_bfloat162 hp; hp.x = h0; hp.y = h1;
                    __nv_bfloat162 lp;
                    lp.x = __float2bfloat16(y0 - __bfloat162float(h0));
                    lp.y = __float2bfloat16(y1 - __bfloat162float(h1));
                    *(uint32_t*)(hout_hi + base) = *reinterpret_cast<uint32_t*>(&hp);
                    *(uint32_t*)(hout_lo + base) = *reinterpret_cast<uint32_t*>(&lp);
                }
            }
        }
    }
}

// ---------------------------------------------------------------------------
// Host
// ---------------------------------------------------------------------------
extern "C" void kernel_launch(void* const* d_in, const int* in_sizes, int n_in,
                              void* d_out, int out_size) {
    const float* x  = (const float*)d_in[0];
    const int*   sp = (const int*)  d_in[1];
    const float* W0 = (const float*)d_in[2];
    const float* b0 = (const float*)d_in[3];
    const float* W1 = (const float*)d_in[4];
    const float* b1 = (const float*)d_in[5];
    const float* W2 = (const float*)d_in[6];
    const float* b2 = (const float*)d_in[7];
    const float* W3 = (const float*)d_in[8];
    const float* b3 = (const float*)d_in[9];
    const float* Wl = (const float*)d_in[10];
    const float* bl = (const float*)d_in[11];
    float* out = (float*)d_out;

    __nv_bfloat16 *h1hi, *h1lo, *h2hi, *h2lo, *h3hi, *h3lo, *h4hi, *h4lo;
    __nv_bfloat16 *w1hi, *w1lo, *w2hi, *w2lo, *w3hi, *w3lo, *wlhi, *wllo;
    float *wt0;
    cudaGetSymbolAddress((void**)&h1hi, g_h1hi);  cudaGetSymbolAddress((void**)&h1lo, g_h1lo);
    cudaGetSymbolAddress((void**)&h2hi, g_h2hi);  cudaGetSymbolAddress((void**)&h2lo, g_h2lo);
    cudaGetSymbolAddress((void**)&h3hi, g_h3hi);  cudaGetSymbolAddress((void**)&h3lo, g_h3lo);
    cudaGetSymbolAddress((void**)&h4hi, g_h4hi);  cudaGetSymbolAddress((void**)&h4lo, g_h4lo);
    cudaGetSymbolAddress((void**)&w1hi, g_w1hi);  cudaGetSymbolAddress((void**)&w1lo, g_w1lo);
    cudaGetSymbolAddress((void**)&w2hi, g_w2hi);  cudaGetSymbolAddress((void**)&w2lo, g_w2lo);
    cudaGetSymbolAddress((void**)&w3hi, g_w3hi);  cudaGetSymbolAddress((void**)&w3lo, g_w3lo);
    cudaGetSymbolAddress((void**)&wlhi, g_wlhi);  cudaGetSymbolAddress((void**)&wllo, g_wllo);
    cudaGetSymbolAddress((void**)&wt0,  g_wt0);

    // ---- fused weight prep (1 launch) ----
    {
        const int total = 864 + 64 * 320 + 128 * 576 + 128 * 1152 + 256 * 128;
        prep_weights<<<(total + 255) / 256, 256>>>(W0, wt0, W1, w1hi, w1lo,
                                                   W2, w2hi, w2lo, W3, w3hi, w3lo,
                                                   Wl, wlhi, wllo);
    }

    const int* sp0 = sp + 0 * NVERT * SP;
    const int* sp1 = sp + 1 * NVERT * SP;
    const int* sp2 = sp + 2 * NVERT * SP;
    const int* sp3 = sp + 3 * NVERT * SP;

    const int grid4 = (NVERT + 3) / 4;   // 1256
    const int grid2 = (NVERT + 1) / 2;   // 2512

    // ---- Layer 0 (SIMT) ----
    {
        constexpr int smb = (128 * 28 + 27 * 32) * 4 + 64 * 4;
        layer0_kernel<<<grid4, 128, smb>>>(x, sp0, wt0, b0, h1hi, h1lo);
    }
    // ---- Layer 1: 32 -> 64, K=288 (pad 320), M=128, 3-stage ----
    {
        auto k = mma_layer<32, 64, 288, 320, 4, 4, 2, 3, true, false>;
        constexpr int smb = 2048 + 6 * (128 * 64) + 6 * (64 * 64);   // 75776
        cudaFuncSetAttribute((const void*)k, cudaFuncAttributeMaxDynamicSharedMemorySize, smb);
        k<<<grid4, 256, smb>>>(h1hi, h1lo, sp1, w1hi, w1lo, b1, h2hi, h2lo, nullptr);
    }
    // ---- Layer 2: 64 -> 128, K=576, M=128, 3-stage ----
    {
        auto k = mma_layer<64, 128, 576, 576, 4, 2, 4, 3, true, false>;
        constexpr int smb = 2048 + 6 * (128 * 64) + 6 * (128 * 64);  // 100352
        cudaFuncSetAttribute((const void*)k, cudaFuncAttributeMaxDynamicSharedMemorySize, smb);
        k<<<grid4, 256, smb>>>(h2hi, h2lo, sp2, w2hi, w2lo, b2, h3hi, h3lo, nullptr);
    }
    // ---- Layer 3: 128 -> 128, K=1152, M=128, 3-stage ----
    {
        auto k = mma_layer<128, 128, 1152, 1152, 4, 2, 4, 3, true, false>;
        constexpr int smb = 2048 + 6 * (128 * 64) + 6 * (128 * 64);  // 100352
        cudaFuncSetAttribute((const void*)k, cudaFuncAttributeMaxDynamicSharedMemorySize, smb);
        k<<<grid4, 256, smb>>>(h3hi, h3lo, sp3, w3hi, w3lo, b3, h4hi, h4lo, nullptr);
    }
    // ---- Final: 128 -> 256, no gather, M=64, 2-stage ----
    {
        auto k = mma_layer<128, 256, 128, 128, 2, 2, 4, 2, false, true>;
        constexpr int smb = 2048 + 4 * (64 * 64) + 4 * (256 * 64);   // 83968
        cudaFuncSetAttribute((const void*)k, cudaFuncAttributeMaxDynamicSharedMemorySize, smb);
        k<<<grid2, 256, smb>>>(h4hi, h4lo, nullptr, wlhi, wllo, bl, nullptr, nullptr, out);
    }
}

// round 10
// speedup vs baseline: 1.4632x; 1.0472x over previous
#include <cuda_runtime.h>
#include <cuda_bf16.h>
#include <cstdint>
#include <cstddef>

static constexpr int BATCH = 32;
static constexpr int NVERT = 5023;
static constexpr int SP    = 9;

// ---------------------------------------------------------------------------
// Helpers (sm_100 base target: mma.sync + ldmatrix + cp.async only)
// ---------------------------------------------------------------------------
__device__ __forceinline__ uint32_t smem_u32(const void* p) {
    uint32_t a;
    asm("{ .reg .u64 t; cvta.to.shared.u64 t, %1; cvt.u32.u64 %0, t; }" : "=r"(a) : "l"(p));
    return a;
}
__device__ __forceinline__ void cp16(uint32_t dst, const void* src, int srcbytes) {
    asm volatile("cp.async.cg.shared.global [%0], [%1], 16, %2;"
                 :: "r"(dst), "l"(src), "r"(srcbytes));
}
__device__ __forceinline__ void cp_commit() {
    asm volatile("cp.async.commit_group;" ::: "memory");
}
template<int N> __device__ __forceinline__ void cp_wait() {
    if constexpr (N == 0) asm volatile("cp.async.wait_group 0;" ::: "memory");
    else if constexpr (N == 1) asm volatile("cp.async.wait_group 1;" ::: "memory");
    else asm volatile("cp.async.wait_group 2;" ::: "memory");
}
__device__ __forceinline__ void ldm4(uint32_t addr, uint32_t* r) {
    asm volatile("ldmatrix.sync.aligned.m8n8.x4.shared.b16 {%0,%1,%2,%3}, [%4];"
                 : "=r"(r[0]), "=r"(r[1]), "=r"(r[2]), "=r"(r[3]) : "r"(addr));
}
__device__ __forceinline__ void mma16816(float* d, const uint32_t* a, const uint32_t* b) {
    asm volatile("mma.sync.aligned.m16n8k16.row.col.f32.bf16.bf16.f32 "
                 "{%0,%1,%2,%3}, {%4,%5,%6,%7}, {%8,%9}, {%0,%1,%2,%3};"
                 : "+f"(d[0]), "+f"(d[1]), "+f"(d[2]), "+f"(d[3])
                 : "r"(a[0]), "r"(a[1]), "r"(a[2]), "r"(a[3]), "r"(b[0]), "r"(b[1]));
}
// SW64 swizzle for 64-byte rows (8 rows x 64B atom = 512B)
__device__ __forceinline__ uint32_t swz64(uint32_t off) { return off ^ ((off >> 3) & 0x30); }

// ---------------------------------------------------------------------------
// Device global scratch
// ---------------------------------------------------------------------------
__device__ __nv_bfloat16 g_h1hi[(size_t)BATCH * NVERT * 32];
__device__ __nv_bfloat16 g_h1lo[(size_t)BATCH * NVERT * 32];
__device__ __nv_bfloat16 g_h2hi[(size_t)BATCH * NVERT * 64];
__device__ __nv_bfloat16 g_h2lo[(size_t)BATCH * NVERT * 64];
__device__ __nv_bfloat16 g_h3hi[(size_t)BATCH * NVERT * 128];
__device__ __nv_bfloat16 g_h3lo[(size_t)BATCH * NVERT * 128];
__device__ __nv_bfloat16 g_h4hi[(size_t)BATCH * NVERT * 128];
__device__ __nv_bfloat16 g_h4lo[(size_t)BATCH * NVERT * 128];

__device__ float g_wt0[27 * 32];
__device__ __nv_bfloat16 g_w1hi[64 * 288],   g_w1lo[64 * 288];
__device__ __nv_bfloat16 g_w2hi[128 * 576],  g_w2lo[128 * 576];
__device__ __nv_bfloat16 g_w3hi[128 * 1152], g_w3lo[128 * 1152];
__device__ __nv_bfloat16 g_wlhi[256 * 128],  g_wllo[256 * 128];

// ---------------------------------------------------------------------------
// Fused weight-prep kernel
// ---------------------------------------------------------------------------
__global__ void prep_weights(const float* W0, float* wt0,
                             const float* W1, __nv_bfloat16* w1hi, __nv_bfloat16* w1lo,
                             const float* W2, __nv_bfloat16* w2hi, __nv_bfloat16* w2lo,
                             const float* W3, __nv_bfloat16* w3hi, __nv_bfloat16* w3lo,
                             const float* Wl, __nv_bfloat16* wlhi, __nv_bfloat16* wllo) {
    int t = blockIdx.x * blockDim.x + threadIdx.x;
    if (t < 864) {
        int k = t / 32, o = t - k * 32;
        wt0[t] = W0[o * 27 + k];
        return;
    }
    t -= 864;
    const float* W; __nv_bfloat16* hi; __nv_bfloat16* lo; int K, KPAD;
    if (t < 64 * 288)                       { W = W1; hi = w1hi; lo = w1lo; K = 288;  KPAD = 288;  }
    else if ((t -= 64 * 288)  < 128 * 576)  { W = W2; hi = w2hi; lo = w2lo; K = 576;  KPAD = 576;  }
    else if ((t -= 128 * 576) < 128 * 1152) { W = W3; hi = w3hi; lo = w3lo; K = 1152; KPAD = 1152; }
    else if ((t -= 128 * 1152) < 256 * 128) { W = Wl; hi = wlhi; lo = wllo; K = 128;  KPAD = 128;  }
    else return;
    int o = t / KPAD, k = t - o * KPAD;
    float w = (k < K) ? W[o * K + k] : 0.f;
    __nv_bfloat16 h = __float2bfloat16(w);
    hi[t] = h;
    lo[t] = __float2bfloat16(w - __bfloat162float(h));
}

// ---------------------------------------------------------------------------
// Layer 0 (SIMT fp32, tiny): 3 -> 32, emits hi/lo bf16 planes
// ---------------------------------------------------------------------------
__global__ void __launch_bounds__(128)
layer0_kernel(const float* __restrict__ x,
              const int*   __restrict__ sidx_g,
              const float* __restrict__ Wt,
              const float* __restrict__ bias,
              __nv_bfloat16* __restrict__ hout_hi,
              __nv_bfloat16* __restrict__ hout_lo) {
    constexpr int IN_C = 3, OUT_C = 32, KC = 27, ROWS = 128, TM = 8, TN = 4;
    constexpr int TX = OUT_C / TN;
    constexpr int NT = 128;
    constexpr int AS = KC + 1;

    extern __shared__ __align__(1024) char dsm[];
    float* Asm = (float*)dsm;
    float* Wsm = Asm + ROWS * AS;
    int*   sidx = (int*)(Wsm + KC * OUT_C);

    const int tid = threadIdx.x;
    const int tx = tid % TX, ty = tid / TX;
    const int v0 = blockIdx.x * 4;

    if (tid < 36) {
        int vt = tid / SP, s = tid - vt * SP;
        int v = v0 + vt; if (v >= NVERT) v = NVERT - 1;
        sidx[tid] = sidx_g[v * SP + s];
    }
    for (int t = tid; t < KC * OUT_C; t += NT) Wsm[t] = Wt[t];
    __syncthreads();
    for (int t = tid; t < ROWS * KC; t += NT) {
        int r = t / KC, kk = t - r * KC;
        int vt = r >> 5, b = r & 31;
        int s = kk / IN_C, c = kk - s * IN_C;
        int srow = sidx[vt * SP + s];
        Asm[r * AS + kk] = x[((size_t)b * NVERT + srow) * IN_C + c];
    }
    __syncthreads();

    float acc[TM][TN];
#pragma unroll
    for (int i = 0; i < TM; ++i)
#pragma unroll
        for (int j = 0; j < TN; ++j) acc[i][j] = 0.f;

#pragma unroll
    for (int k = 0; k < KC; ++k) {
        float a[TM];
#pragma unroll
        for (int i = 0; i < TM; ++i) a[i] = Asm[(ty * TM + i) * AS + k];
        float4 wv = *(const float4*)(Wsm + k * OUT_C + tx * TN);
        float w[TN] = {wv.x, wv.y, wv.z, wv.w};
#pragma unroll
        for (int i = 0; i < TM; ++i)
#pragma unroll
            for (int j = 0; j < TN; ++j) acc[i][j] += a[i] * w[j];
    }

#pragma unroll
    for (int i = 0; i < TM; ++i) {
        int r = ty * TM + i;
        int vt = r >> 5, b = r & 31;
        int v = v0 + vt;
        if (v < NVERT) {
            size_t off = ((size_t)b * NVERT + v) * OUT_C + tx * TN;
#pragma unroll
            for (int j = 0; j < TN; ++j) {
                float y = acc[i][j] + __ldg(&bias[tx * TN + j]);
                __nv_bfloat16 h = __float2bfloat16(y);
                hout_hi[off + j] = h;
                hout_lo[off + j] = __float2bfloat16(y - __bfloat162float(h));
            }
        }
    }
}

// ---------------------------------------------------------------------------
// HMMA bf16-split layer. NT = 32*WRG*WCG threads, max-blocks = 512/NT
// (256 thr -> 2 CTAs/SM, 128 thr -> 4 CTAs/SM). KC=32, NSTAGE-deep cp.async
// pipeline, prefetch ISSUED BEFORE the wait. Two NT-thread barriers per chunk.
// 3 MMA passes per k16: AhiBhi + AhiBlo + AloBhi.
// smem header: [0,256) sidx, [256,1280) bias, [2048...) tiles.
// ---------------------------------------------------------------------------
template<int IN_C, int OUT_C, int KREAL, int KPAD, int MV, int WRG, int WCG,
         int NSTAGE, bool GATHER, bool FINAL>
__global__ void __launch_bounds__(32 * WRG * WCG, 512 / (32 * WRG * WCG))
mma_layer(const __nv_bfloat16* __restrict__ hin_hi,
          const __nv_bfloat16* __restrict__ hin_lo,
          const int*           __restrict__ sidx_g,
          const __nv_bfloat16* __restrict__ whi,
          const __nv_bfloat16* __restrict__ wlo,
          const float*         __restrict__ bias,
          __nv_bfloat16*       __restrict__ hout_hi,
          __nv_bfloat16*       __restrict__ hout_lo,
          float*               __restrict__ fout) {
    constexpr int NT    = 32 * WRG * WCG;
    constexpr int MROWS = MV * 32;
    constexpr int NCH   = KPAD / 32;
    constexpr int ATB   = MROWS * 64;       // bytes per A plane-buffer (64B rows)
    constexpr int BTB   = OUT_C * 64;       // bytes per B plane-buffer
    constexpr int SM_A  = 2048;             // after sidx [0,256) + bias [256,1280)
    constexpr int SM_B  = SM_A + 2 * NSTAGE * ATB;
    constexpr int WARP_R = MROWS / WRG;
    constexpr int WARP_C = OUT_C / WCG;
    constexpr int RS = WARP_R / 16;
    constexpr int NO = WARP_C / 8;
    constexpr int TOT_A = MROWS * 4 * 2;    // 16B tasks (4 units/row, 2 planes)
    constexpr int TOT_B = OUT_C * 4 * 2;

    extern __shared__ __align__(1024) char dsm[];
    const uint32_t sbase = smem_u32(dsm);
    int*   sidx = (int*)dsm;                // MV*9 ints (<= 36) @ [0,256)
    float* bsm  = (float*)(dsm + 256);      // OUT_C floats (<=256) @ [256,1280)

    const int tid  = threadIdx.x;
    const int wid  = tid >> 5;
    const int lane = tid & 31;
    const int v0   = blockIdx.x * MV;

    const int wr = wid % WRG, wc = wid / WRG;
    const int warp_r0 = wr * WARP_R;
    const int warp_c0 = wc * WARP_C;

    if (GATHER && tid < MV * SP) {
        int vt = tid / SP, s = tid - vt * SP;
        int v = v0 + vt; if (v >= NVERT) v = NVERT - 1;
        sidx[tid] = sidx_g[v * SP + s];
    }
    for (int t = tid; t < OUT_C; t += NT) bsm[t] = bias[t];
    __syncthreads();

    // ---- chunk loader into pipeline stage st ----
    auto load_chunk = [&](int ch, int st) {
#pragma unroll
        for (int t = tid; t < TOT_A; t += NT) {
            int plane = t >= MROWS * 4;
            int rg = plane ? t - MROWS * 4 : t;
            int r = rg >> 2, g = rg & 3;
            int vt = r >> 5, b = r & 31;
            int kg = ch * 32 + g * 8;
            int kgc = kg < KREAL ? kg : 0;
            int s = GATHER ? kgc / IN_C : 0;
            int c = GATHER ? kgc - s * IN_C : kgc;
            int v = v0 + vt; if (v >= NVERT) v = NVERT - 1;
            int srow = GATHER ? sidx[vt * SP + s] : v;
            const __nv_bfloat16* src = (plane ? hin_lo : hin_hi)
                + ((size_t)b * NVERT + srow) * IN_C + c;
            uint32_t dst = sbase + SM_A + (uint32_t)(st * 2 + plane) * ATB
                         + swz64((uint32_t)(r * 64 + g * 16));
            cp16(dst, src, kg < KREAL ? 16 : 0);
        }
#pragma unroll
        for (int t = tid; t < TOT_B; t += NT) {
            int plane = t >= OUT_C * 4;
            int rg = plane ? t - OUT_C * 4 : t;
            int n = rg >> 2, g = rg & 3;
            int kg = ch * 32 + g * 8;
            const __nv_bfloat16* src = (plane ? wlo : whi) + (size_t)n * KPAD + kg;
            uint32_t dst = sbase + SM_B + (uint32_t)(st * 2 + plane) * BTB
                         + swz64((uint32_t)(n * 64 + g * 16));
            cp16(dst, src, 16);
        }
        cp_commit();
    };

    float acc[RS][NO][4];
#pragma unroll
    for (int i = 0; i < RS; ++i)
#pragma unroll
        for (int j = 0; j < NO; ++j)
#pragma unroll
            for (int q = 0; q < 4; ++q) acc[i][j][q] = 0.f;

    const int grp = lane >> 3, lr = lane & 7;

#pragma unroll
    for (int i = 0; i < NSTAGE - 1; ++i) load_chunk(i, i);

    for (int ch = 0; ch < NCH; ++ch) {
        const int st = ch % NSTAGE;

        // issue prefetch BEFORE waiting: overlaps addr math + cp issue with
        // the in-flight groups. Target stage was freed by the trailing
        // barrier of the previous iteration.
        if (ch + NSTAGE - 1 < NCH) load_chunk(ch + NSTAGE - 1, (ch + NSTAGE - 1) % NSTAGE);
        else                       cp_commit();   // keep group counts aligned

        cp_wait<NSTAGE - 1>();   // chunk ch complete (NSTAGE-1 newer pending)
        __syncthreads();         // chunk ch visible to all warps

        const uint32_t Ahi = sbase + SM_A + (uint32_t)(st * 2 + 0) * ATB;
        const uint32_t Alo = sbase + SM_A + (uint32_t)(st * 2 + 1) * ATB;
        const uint32_t Bhi = sbase + SM_B + (uint32_t)(st * 2 + 0) * BTB;
        const uint32_t Blo = sbase + SM_B + (uint32_t)(st * 2 + 1) * BTB;

#pragma unroll
        for (int ks = 0; ks < 2; ++ks) {            // 2 k16 steps per chunk
            uint32_t bh[NO][2], bl_[NO][2];
#pragma unroll
            for (int p16 = 0; p16 < NO / 2; ++p16) {
                int n  = warp_c0 + p16 * 16 + (grp >> 1) * 8 + lr;
                int c16 = ks * 2 + (grp & 1);
                uint32_t off = swz64((uint32_t)(n * 64 + c16 * 16));
                uint32_t m[4];
                ldm4(Bhi + off, m);
                bh[2 * p16][0] = m[0]; bh[2 * p16][1] = m[1];
                bh[2 * p16 + 1][0] = m[2]; bh[2 * p16 + 1][1] = m[3];
                ldm4(Blo + off, m);
                bl_[2 * p16][0] = m[0]; bl_[2 * p16][1] = m[1];
                bl_[2 * p16 + 1][0] = m[2]; bl_[2 * p16 + 1][1] = m[3];
            }
#pragma unroll
            for (int sub = 0; sub < RS; ++sub) {
                int row = warp_r0 + sub * 16 + (grp & 1) * 8 + lr;
                int c16 = ks * 2 + (grp >> 1);
                uint32_t off = swz64((uint32_t)(row * 64 + c16 * 16));
                uint32_t ah[4], al[4];
                ldm4(Ahi + off, ah);
                ldm4(Alo + off, al);
#pragma unroll
                for (int oct = 0; oct < NO; ++oct) {
                    mma16816(acc[sub][oct], ah, bh[oct]);
                    mma16816(acc[sub][oct], ah, bl_[oct]);
                    mma16816(acc[sub][oct], al, bh[oct]);
                }
            }
        }
        __syncthreads();         // all warps done with stage st before refill
    }

    // ---- epilogue: bias + (re-split | f32) stores straight from D frags ----
    const int tq = lane >> 2, tr = lane & 3;
#pragma unroll
    for (int sub = 0; sub < RS; ++sub) {
#pragma unroll
        for (int half = 0; half < 2; ++half) {
            int r = warp_r0 + sub * 16 + half * 8 + tq;
            int vt = r >> 5, b = r & 31;
            int v = v0 + vt;
            if (v >= NVERT) continue;
#pragma unroll
            for (int oct = 0; oct < NO; ++oct) {
                int col = warp_c0 + oct * 8 + tr * 2;
                float y0 = acc[sub][oct][2 * half]     + bsm[col];
                float y1 = acc[sub][oct][2 * half + 1] + bsm[col + 1];
                size_t base = ((size_t)b * NVERT + v) * OUT_C + col;
                if (FINAL) {
                    *(float2*)(fout + base) = make_float2(y0, y1);
                } else {
                    __nv_bfloat16 h0 = __float2bfloat16(y0);
                    __nv_bfloat16 h1 = __float2bfloat16(y1);
                    __nv_bfloat162 hp; hp.x = h0; hp.y = h1;
                    __nv_bfloat162 lp;
                    lp.x = __float2bfloat16(y0 - __bfloat162float(h0));
                    lp.y = __float2bfloat16(y1 - __bfloat162float(h1));
                    *(uint32_t*)(hout_hi + base) = *reinterpret_cast<uint32_t*>(&hp);
                    *(uint32_t*)(hout_lo + base) = *reinterpret_cast<uint32_t*>(&lp);
                }
            }
        }
    }
}

// ---------------------------------------------------------------------------
// Host
// ---------------------------------------------------------------------------
extern "C" void kernel_launch(void* const* d_in, const int* in_sizes, int n_in,
                              void* d_out, int out_size) {
    const float* x  = (const float*)d_in[0];
    const int*   sp = (const int*)  d_in[1];
    const float* W0 = (const float*)d_in[2];
    const float* b0 = (const float*)d_in[3];
    const float* W1 = (const float*)d_in[4];
    const float* b1 = (const float*)d_in[5];
    const float* W2 = (const float*)d_in[6];
    const float* b2 = (const float*)d_in[7];
    const float* W3 = (const float*)d_in[8];
    const float* b3 = (const float*)d_in[9];
    const float* Wl = (const float*)d_in[10];
    const float* bl = (const float*)d_in[11];
    float* out = (float*)d_out;

    __nv_bfloat16 *h1hi, *h1lo, *h2hi, *h2lo, *h3hi, *h3lo, *h4hi, *h4lo;
    __nv_bfloat16 *w1hi, *w1lo, *w2hi, *w2lo, *w3hi, *w3lo, *wlhi, *wllo;
    float *wt0;
    cudaGetSymbolAddress((void**)&h1hi, g_h1hi);  cudaGetSymbolAddress((void**)&h1lo, g_h1lo);
    cudaGetSymbolAddress((void**)&h2hi, g_h2hi);  cudaGetSymbolAddress((void**)&h2lo, g_h2lo);
    cudaGetSymbolAddress((void**)&h3hi, g_h3hi);  cudaGetSymbolAddress((void**)&h3lo, g_h3lo);
    cudaGetSymbolAddress((void**)&h4hi, g_h4hi);  cudaGetSymbolAddress((void**)&h4lo, g_h4lo);
    cudaGetSymbolAddress((void**)&w1hi, g_w1hi);  cudaGetSymbolAddress((void**)&w1lo, g_w1lo);
    cudaGetSymbolAddress((void**)&w2hi, g_w2hi);  cudaGetSymbolAddress((void**)&w2lo, g_w2lo);
    cudaGetSymbolAddress((void**)&w3hi, g_w3hi);  cudaGetSymbolAddress((void**)&w3lo, g_w3lo);
    cudaGetSymbolAddress((void**)&wlhi, g_wlhi);  cudaGetSymbolAddress((void**)&wllo, g_wllo);
    cudaGetSymbolAddress((void**)&wt0,  g_wt0);

    // ---- fused weight prep (1 launch) ----
    {
        const int total = 864 + 64 * 288 + 128 * 576 + 128 * 1152 + 256 * 128;
        prep_weights<<<(total + 255) / 256, 256>>>(W0, wt0, W1, w1hi, w1lo,
                                                   W2, w2hi, w2lo, W3, w3hi, w3lo,
                                                   Wl, wlhi, wllo);
    }

    const int* sp0 = sp + 0 * NVERT * SP;
    const int* sp1 = sp + 1 * NVERT * SP;
    const int* sp2 = sp + 2 * NVERT * SP;
    const int* sp3 = sp + 3 * NVERT * SP;

    const int grid4 = (NVERT + 3) / 4;   // 1256
    const int grid2 = (NVERT + 1) / 2;   // 2512

    // ---- Layer 0 (SIMT) ----
    {
        constexpr int smb = (128 * 28 + 27 * 32) * 4 + 64 * 4;
        layer0_kernel<<<grid4, 128, smb>>>(x, sp0, wt0, b0, h1hi, h1lo);
    }
    // ---- Layer 1: 32 -> 64, K=288 (no pad), M=128, 256 thr, 3-stage ----
    {
        auto k = mma_layer<32, 64, 288, 288, 4, 4, 2, 3, true, false>;
        constexpr int smb = 2048 + 6 * (128 * 64) + 6 * (64 * 64);   // 75776
        cudaFuncSetAttribute((const void*)k, cudaFuncAttributeMaxDynamicSharedMemorySize, smb);
        k<<<grid4, 256, smb>>>(h1hi, h1lo, sp1, w1hi, w1lo, b1, h2hi, h2lo, nullptr);
    }
    // ---- Layer 2: 64 -> 128, K=576, M=64, 128 thr (4 CTA/SM), 2-stage ----
    {
        auto k = mma_layer<64, 128, 576, 576, 2, 1, 4, 2, true, false>;
        constexpr int smb = 2048 + 4 * (64 * 64) + 4 * (128 * 64);   // 51200
        cudaFuncSetAttribute((const void*)k, cudaFuncAttributeMaxDynamicSharedMemorySize, smb);
        k<<<grid2, 128, smb>>>(h2hi, h2lo, sp2, w2hi, w2lo, b2, h3hi, h3lo, nullptr);
    }
    // ---- Layer 3: 128 -> 128, K=1152, M=64, 128 thr (4 CTA/SM), 2-stage ----
    {
        auto k = mma_layer<128, 128, 1152, 1152, 2, 1, 4, 2, true, false>;
        constexpr int smb = 2048 + 4 * (64 * 64) + 4 * (128 * 64);   // 51200
        cudaFuncSetAttribute((const void*)k, cudaFuncAttributeMaxDynamicSharedMemorySize, smb);
        k<<<grid2, 128, smb>>>(h3hi, h3lo, sp3, w3hi, w3lo, b3, h4hi, h4lo, nullptr);
    }
    // ---- Final: 128 -> 256, no gather, M=64, 256 thr, 2-stage ----
    {
        auto k = mma_layer<128, 256, 128, 128, 2, 2, 4, 2, false, true>;
        constexpr int smb = 2048 + 4 * (64 * 64) + 4 * (256 * 64);   // 83968
        cudaFuncSetAttribute((const void*)k, cudaFuncAttributeMaxDynamicSharedMemorySize, smb);
        k<<<grid2, 256, smb>>>(h4hi, h4lo, nullptr, wlhi, wllo, bl, nullptr, nullptr, out);
    }
}

// round 11
// speedup vs baseline: 1.8033x; 1.2324x over previous
#include <cuda_runtime.h>
#include <cuda_bf16.h>
#include <cuda_fp16.h>
#include <cstdint>
#include <cstddef>

static constexpr int BATCH = 32;
static constexpr int NVERT = 5023;
static constexpr int SP    = 9;

// ---------------------------------------------------------------------------
// Helpers (sm_100 base target: mma.sync + ldmatrix + cp.async only)
// ---------------------------------------------------------------------------
__device__ __forceinline__ uint32_t smem_u32(const void* p) {
    uint32_t a;
    asm("{ .reg .u64 t; cvta.to.shared.u64 t, %1; cvt.u32.u64 %0, t; }" : "=r"(a) : "l"(p));
    return a;
}
__device__ __forceinline__ void cp16(uint32_t dst, const void* src, int srcbytes) {
    asm volatile("cp.async.cg.shared.global [%0], [%1], 16, %2;"
                 :: "r"(dst), "l"(src), "r"(srcbytes));
}
__device__ __forceinline__ void cp_commit() {
    asm volatile("cp.async.commit_group;" ::: "memory");
}
template<int N> __device__ __forceinline__ void cp_wait() {
    if constexpr (N == 0) asm volatile("cp.async.wait_group 0;" ::: "memory");
    else if constexpr (N == 1) asm volatile("cp.async.wait_group 1;" ::: "memory");
    else asm volatile("cp.async.wait_group 2;" ::: "memory");
}
__device__ __forceinline__ void ldm4(uint32_t addr, uint32_t* r) {
    asm volatile("ldmatrix.sync.aligned.m8n8.x4.shared.b16 {%0,%1,%2,%3}, [%4];"
                 : "=r"(r[0]), "=r"(r[1]), "=r"(r[2]), "=r"(r[3]) : "r"(addr));
}
__device__ __forceinline__ void mma_bf16(float* d, const uint32_t* a, const uint32_t* b) {
    asm volatile("mma.sync.aligned.m16n8k16.row.col.f32.bf16.bf16.f32 "
                 "{%0,%1,%2,%3}, {%4,%5,%6,%7}, {%8,%9}, {%0,%1,%2,%3};"
                 : "+f"(d[0]), "+f"(d[1]), "+f"(d[2]), "+f"(d[3])
                 : "r"(a[0]), "r"(a[1]), "r"(a[2]), "r"(a[3]), "r"(b[0]), "r"(b[1]));
}
__device__ __forceinline__ void mma_fp16(float* d, const uint32_t* a, const uint32_t* b) {
    asm volatile("mma.sync.aligned.m16n8k16.row.col.f32.f16.f16.f32 "
                 "{%0,%1,%2,%3}, {%4,%5,%6,%7}, {%8,%9}, {%0,%1,%2,%3};"
                 : "+f"(d[0]), "+f"(d[1]), "+f"(d[2]), "+f"(d[3])
                 : "r"(a[0]), "r"(a[1]), "r"(a[2]), "r"(a[3]), "r"(b[0]), "r"(b[1]));
}
// SW64 swizzle for 64-byte rows (8 rows x 64B atom = 512B)
__device__ __forceinline__ uint32_t swz64(uint32_t off) { return off ^ ((off >> 3) & 0x30); }

// ---------------------------------------------------------------------------
// Device global scratch (all activation elements are 2 bytes)
// ---------------------------------------------------------------------------
__device__ __nv_bfloat16 g_h1hi[(size_t)BATCH * NVERT * 32];
__device__ __nv_bfloat16 g_h1lo[(size_t)BATCH * NVERT * 32];
__device__ __half        g_h2  [(size_t)BATCH * NVERT * 64];    // fp16 single plane
__device__ __half        g_h3  [(size_t)BATCH * NVERT * 128];   // fp16 single plane
__device__ __nv_bfloat16 g_h4hi[(size_t)BATCH * NVERT * 128];
__device__ __nv_bfloat16 g_h4lo[(size_t)BATCH * NVERT * 128];

__device__ float g_wt0[27 * 32];
__device__ __nv_bfloat16 g_w1hi[64 * 288],   g_w1lo[64 * 288];
__device__ __half        g_w2hi[128 * 576],  g_w2lo[128 * 576];
__device__ __half        g_w3hi[128 * 1152], g_w3lo[128 * 1152];
__device__ __nv_bfloat16 g_wlhi[256 * 128],  g_wllo[256 * 128];

// ---------------------------------------------------------------------------
// Fused weight-prep kernel (bf16 split for W1/Wl, fp16 split for W2/W3)
// ---------------------------------------------------------------------------
__global__ void prep_weights(const float* W0, float* wt0,
                             const float* W1, __nv_bfloat16* w1hi, __nv_bfloat16* w1lo,
                             const float* W2, __half* w2hi, __half* w2lo,
                             const float* W3, __half* w3hi, __half* w3lo,
                             const float* Wl, __nv_bfloat16* wlhi, __nv_bfloat16* wllo) {
    int t = blockIdx.x * blockDim.x + threadIdx.x;
    if (t < 864) {
        int k = t / 32, o = t - k * 32;
        wt0[t] = W0[o * 27 + k];
        return;
    }
    t -= 864;
    if (t < 64 * 288) {
        int o = t / 288, k = t - o * 288;
        float w = W1[o * 288 + k];
        __nv_bfloat16 h = __float2bfloat16(w);
        w1hi[t] = h; w1lo[t] = __float2bfloat16(w - __bfloat162float(h));
        return;
    }
    t -= 64 * 288;
    if (t < 128 * 576) {
        float w = W2[t];
        __half h = __float2half_rn(w);
        w2hi[t] = h; w2lo[t] = __float2half_rn(w - __half2float(h));
        return;
    }
    t -= 128 * 576;
    if (t < 128 * 1152) {
        float w = W3[t];
        __half h = __float2half_rn(w);
        w3hi[t] = h; w3lo[t] = __float2half_rn(w - __half2float(h));
        return;
    }
    t -= 128 * 1152;
    if (t < 256 * 128) {
        float w = Wl[t];
        __nv_bfloat16 h = __float2bfloat16(w);
        wlhi[t] = h; wllo[t] = __float2bfloat16(w - __bfloat162float(h));
    }
}

// ---------------------------------------------------------------------------
// Layer 0 (SIMT fp32, tiny): 3 -> 32, emits hi/lo bf16 planes
// ---------------------------------------------------------------------------
__global__ void __launch_bounds__(128)
layer0_kernel(const float* __restrict__ x,
              const int*   __restrict__ sidx_g,
              const float* __restrict__ Wt,
              const float* __restrict__ bias,
              __nv_bfloat16* __restrict__ hout_hi,
              __nv_bfloat16* __restrict__ hout_lo) {
    constexpr int IN_C = 3, OUT_C = 32, KC = 27, ROWS = 128, TM = 8, TN = 4;
    constexpr int TX = OUT_C / TN;
    constexpr int NT = 128;
    constexpr int AS = KC + 1;

    extern __shared__ __align__(1024) char dsm[];
    float* Asm = (float*)dsm;
    float* Wsm = Asm + ROWS * AS;
    int*   sidx = (int*)(Wsm + KC * OUT_C);

    const int tid = threadIdx.x;
    const int tx = tid % TX, ty = tid / TX;
    const int v0 = blockIdx.x * 4;

    if (tid < 36) {
        int vt = tid / SP, s = tid - vt * SP;
        int v = v0 + vt; if (v >= NVERT) v = NVERT - 1;
        sidx[tid] = sidx_g[v * SP + s];
    }
    for (int t = tid; t < KC * OUT_C; t += NT) Wsm[t] = Wt[t];
    __syncthreads();
    for (int t = tid; t < ROWS * KC; t += NT) {
        int r = t / KC, kk = t - r * KC;
        int vt = r >> 5, b = r & 31;
        int s = kk / IN_C, c = kk - s * IN_C;
        int srow = sidx[vt * SP + s];
        Asm[r * AS + kk] = x[((size_t)b * NVERT + srow) * IN_C + c];
    }
    __syncthreads();

    float acc[TM][TN];
#pragma unroll
    for (int i = 0; i < TM; ++i)
#pragma unroll
        for (int j = 0; j < TN; ++j) acc[i][j] = 0.f;

#pragma unroll
    for (int k = 0; k < KC; ++k) {
        float a[TM];
#pragma unroll
        for (int i = 0; i < TM; ++i) a[i] = Asm[(ty * TM + i) * AS + k];
        float4 wv = *(const float4*)(Wsm + k * OUT_C + tx * TN);
        float w[TN] = {wv.x, wv.y, wv.z, wv.w};
#pragma unroll
        for (int i = 0; i < TM; ++i)
#pragma unroll
            for (int j = 0; j < TN; ++j) acc[i][j] += a[i] * w[j];
    }

#pragma unroll
    for (int i = 0; i < TM; ++i) {
        int r = ty * TM + i;
        int vt = r >> 5, b = r & 31;
        int v = v0 + vt;
        if (v < NVERT) {
            size_t off = ((size_t)b * NVERT + v) * OUT_C + tx * TN;
#pragma unroll
            for (int j = 0; j < TN; ++j) {
                float y = acc[i][j] + __ldg(&bias[tx * TN + j]);
                __nv_bfloat16 h = __float2bfloat16(y);
                hout_hi[off + j] = h;
                hout_lo[off + j] = __float2bfloat16(y - __bfloat162float(h));
            }
        }
    }
}

// ---------------------------------------------------------------------------
// HMMA split-precision layer. All 2-byte dtypes handled via uint16_t pointers.
//   INF16=1: A is a single fp16 plane; 2 MMA passes (Ahi*Bhi + Ahi*Blo).
//   INF16=0: A is bf16 hi/lo planes; 3 MMA passes (AhBh + AhBl + AlBh).
//   OUTMODE: 0 = bf16 hi/lo planes, 1 = fp16 single plane, 2 = f32 final.
// NT = 32*WRG*WCG threads; max-blocks 512/NT. KC=32, NSTAGE-deep cp.async
// pipeline, prefetch ISSUED BEFORE the wait.
// smem header: [0,256) sidx, [256,1280) bias, [2048...) tiles.
// ---------------------------------------------------------------------------
template<int IN_C, int OUT_C, int KPAD, int MV, int WRG, int WCG,
         int NSTAGE, bool GATHER, bool INF16, int OUTMODE>
__global__ void __launch_bounds__(32 * WRG * WCG, 512 / (32 * WRG * WCG))
mma_layer(const uint16_t* __restrict__ hinA,    // hi plane (or sole fp16 plane)
          const uint16_t* __restrict__ hinB,    // lo plane (unused if INF16)
          const int*      __restrict__ sidx_g,
          const uint16_t* __restrict__ whi,
          const uint16_t* __restrict__ wlo,
          const float*    __restrict__ bias,
          void*           __restrict__ outA,    // hi / fp16 / f32 out
          void*           __restrict__ outB) {  // lo plane (bf16 out only)
    constexpr int NT    = 32 * WRG * WCG;
    constexpr int MROWS = MV * 32;
    constexpr int NCH   = KPAD / 32;
    constexpr int APLANES = INF16 ? 1 : 2;
    constexpr int ATB   = MROWS * 64;           // bytes per A plane-buffer
    constexpr int ASTR  = APLANES * ATB;        // A bytes per stage
    constexpr int BTB   = OUT_C * 64;           // bytes per B plane-buffer
    constexpr int SM_A  = 2048;                 // after sidx [0,256) + bias [256,1280)
    constexpr int SM_B  = SM_A + NSTAGE * ASTR;
    constexpr int WARP_R = MROWS / WRG;
    constexpr int WARP_C = OUT_C / WCG;
    constexpr int RS = WARP_R / 16;
    constexpr int NO = WARP_C / 8;
    constexpr int TOT_A = MROWS * 4 * APLANES;  // 16B tasks per chunk
    constexpr int TOT_B = OUT_C * 4 * 2;

    extern __shared__ __align__(1024) char dsm[];
    const uint32_t sbase = smem_u32(dsm);
    int*   sidx = (int*)dsm;
    float* bsm  = (float*)(dsm + 256);

    const int tid  = threadIdx.x;
    const int wid  = tid >> 5;
    const int lane = tid & 31;
    const int v0   = blockIdx.x * MV;

    const int wr = wid % WRG, wc = wid / WRG;
    const int warp_r0 = wr * WARP_R;
    const int warp_c0 = wc * WARP_C;

    if (GATHER && tid < MV * SP) {
        int vt = tid / SP, s = tid - vt * SP;
        int v = v0 + vt; if (v >= NVERT) v = NVERT - 1;
        sidx[tid] = sidx_g[v * SP + s];
    }
    for (int t = tid; t < OUT_C; t += NT) bsm[t] = bias[t];
    __syncthreads();

    // ---- chunk loader into pipeline stage st ----
    auto load_chunk = [&](int ch, int st) {
#pragma unroll
        for (int t = tid; t < TOT_A; t += NT) {
            int plane = INF16 ? 0 : (t >= MROWS * 4);
            int rg = plane ? t - MROWS * 4 : t;
            int r = rg >> 2, g = rg & 3;
            int vt = r >> 5, b = r & 31;
            int kg = ch * 32 + g * 8;
            int s = GATHER ? kg / IN_C : 0;
            int c = GATHER ? kg - s * IN_C : kg;
            int v = v0 + vt; if (v >= NVERT) v = NVERT - 1;
            int srow = GATHER ? sidx[vt * SP + s] : v;
            const uint16_t* src = (plane ? hinB : hinA)
                + ((size_t)b * NVERT + srow) * IN_C + c;
            uint32_t dst = sbase + SM_A + (uint32_t)st * ASTR + (uint32_t)plane * ATB
                         + swz64((uint32_t)(r * 64 + g * 16));
            cp16(dst, src, 16);
        }
#pragma unroll
        for (int t = tid; t < TOT_B; t += NT) {
            int plane = t >= OUT_C * 4;
            int rg = plane ? t - OUT_C * 4 : t;
            int n = rg >> 2, g = rg & 3;
            int kg = ch * 32 + g * 8;
            const uint16_t* src = (plane ? wlo : whi) + (size_t)n * KPAD + kg;
            uint32_t dst = sbase + SM_B + (uint32_t)(st * 2 + plane) * BTB
                         + swz64((uint32_t)(n * 64 + g * 16));
            cp16(dst, src, 16);
        }
        cp_commit();
    };

    float acc[RS][NO][4];
#pragma unroll
    for (int i = 0; i < RS; ++i)
#pragma unroll
        for (int j = 0; j < NO; ++j)
#pragma unroll
            for (int q = 0; q < 4; ++q) acc[i][j][q] = 0.f;

    const int grp = lane >> 3, lr = lane & 7;

#pragma unroll
    for (int i = 0; i < NSTAGE - 1; ++i) load_chunk(i, i);

    for (int ch = 0; ch < NCH; ++ch) {
        const int st = ch % NSTAGE;

        // issue prefetch BEFORE waiting (overlap addr math + cp issue)
        if (ch + NSTAGE - 1 < NCH) load_chunk(ch + NSTAGE - 1, (ch + NSTAGE - 1) % NSTAGE);
        else                       cp_commit();

        cp_wait<NSTAGE - 1>();
        __syncthreads();

        const uint32_t Ahi = sbase + SM_A + (uint32_t)st * ASTR;
        const uint32_t Alo = Ahi + ATB;          // valid only if !INF16
        const uint32_t Bhi = sbase + SM_B + (uint32_t)(st * 2 + 0) * BTB;
        const uint32_t Blo = sbase + SM_B + (uint32_t)(st * 2 + 1) * BTB;

#pragma unroll
        for (int ks = 0; ks < 2; ++ks) {
            uint32_t bh[NO][2], bl_[NO][2];
#pragma unroll
            for (int p16 = 0; p16 < NO / 2; ++p16) {
                int n  = warp_c0 + p16 * 16 + (grp >> 1) * 8 + lr;
                int c16 = ks * 2 + (grp & 1);
                uint32_t off = swz64((uint32_t)(n * 64 + c16 * 16));
                uint32_t m[4];
                ldm4(Bhi + off, m);
                bh[2 * p16][0] = m[0]; bh[2 * p16][1] = m[1];
                bh[2 * p16 + 1][0] = m[2]; bh[2 * p16 + 1][1] = m[3];
                ldm4(Blo + off, m);
                bl_[2 * p16][0] = m[0]; bl_[2 * p16][1] = m[1];
                bl_[2 * p16 + 1][0] = m[2]; bl_[2 * p16 + 1][1] = m[3];
            }
#pragma unroll
            for (int sub = 0; sub < RS; ++sub) {
                int row = warp_r0 + sub * 16 + (grp & 1) * 8 + lr;
                int c16 = ks * 2 + (grp >> 1);
                uint32_t off = swz64((uint32_t)(row * 64 + c16 * 16));
                uint32_t ah[4];
                ldm4(Ahi + off, ah);
                if constexpr (INF16) {
#pragma unroll
                    for (int oct = 0; oct < NO; ++oct) {
                        mma_fp16(acc[sub][oct], ah, bh[oct]);
                        mma_fp16(acc[sub][oct], ah, bl_[oct]);
                    }
                } else {
                    uint32_t al[4];
                    ldm4(Alo + off, al);
#pragma unroll
                    for (int oct = 0; oct < NO; ++oct) {
                        mma_bf16(acc[sub][oct], ah, bh[oct]);
                        mma_bf16(acc[sub][oct], ah, bl_[oct]);
                        mma_bf16(acc[sub][oct], al, bh[oct]);
                    }
                }
            }
        }
        __syncthreads();
    }

    // ---- epilogue: bias + store per OUTMODE ----
    const int tq = lane >> 2, tr = lane & 3;
#pragma unroll
    for (int sub = 0; sub < RS; ++sub) {
#pragma unroll
        for (int half = 0; half < 2; ++half) {
            int r = warp_r0 + sub * 16 + half * 8 + tq;
            int vt = r >> 5, b = r & 31;
            int v = v0 + vt;
            if (v >= NVERT) continue;
#pragma unroll
            for (int oct = 0; oct < NO; ++oct) {
                int col = warp_c0 + oct * 8 + tr * 2;
                float y0 = acc[sub][oct][2 * half]     + bsm[col];
                float y1 = acc[sub][oct][2 * half + 1] + bsm[col + 1];
                size_t base = ((size_t)b * NVERT + v) * OUT_C + col;
                if constexpr (OUTMODE == 2) {
                    *(float2*)((float*)outA + base) = make_float2(y0, y1);
                } else if constexpr (OUTMODE == 1) {
                    __half2 hp = __floats2half2_rn(y0, y1);
                    *(uint32_t*)((__half*)outA + base) = *reinterpret_cast<uint32_t*>(&hp);
                } else {
                    __nv_bfloat16 h0 = __float2bfloat16(y0);
                    __nv_bfloat16 h1 = __float2bfloat16(y1);
                    __nv_bfloat162 hp; hp.x = h0; hp.y = h1;
                    __nv_bfloat162 lp;
                    lp.x = __float2bfloat16(y0 - __bfloat162float(h0));
                    lp.y = __float2bfloat16(y1 - __bfloat162float(h1));
                    *(uint32_t*)((__nv_bfloat16*)outA + base) = *reinterpret_cast<uint32_t*>(&hp);
                    *(uint32_t*)((__nv_bfloat16*)outB + base) = *reinterpret_cast<uint32_t*>(&lp);
                }
            }
        }
    }
}

// ---------------------------------------------------------------------------
// Host
// ---------------------------------------------------------------------------
extern "C" void kernel_launch(void* const* d_in, const int* in_sizes, int n_in,
                              void* d_out, int out_size) {
    const float* x  = (const float*)d_in[0];
    const int*   sp = (const int*)  d_in[1];
    const float* W0 = (const float*)d_in[2];
    const float* b0 = (const float*)d_in[3];
    const float* W1 = (const float*)d_in[4];
    const float* b1 = (const float*)d_in[5];
    const float* W2 = (const float*)d_in[6];
    const float* b2 = (const float*)d_in[7];
    const float* W3 = (const float*)d_in[8];
    const float* b3 = (const float*)d_in[9];
    const float* Wl = (const float*)d_in[10];
    const float* bl = (const float*)d_in[11];
    float* out = (float*)d_out;

    __nv_bfloat16 *h1hi, *h1lo, *h4hi, *h4lo, *w1hi, *w1lo, *wlhi, *wllo;
    __half *h2, *h3, *w2hi, *w2lo, *w3hi, *w3lo;
    float *wt0;
    cudaGetSymbolAddress((void**)&h1hi, g_h1hi);  cudaGetSymbolAddress((void**)&h1lo, g_h1lo);
    cudaGetSymbolAddress((void**)&h2,   g_h2);
    cudaGetSymbolAddress((void**)&h3,   g_h3);
    cudaGetSymbolAddress((void**)&h4hi, g_h4hi);  cudaGetSymbolAddress((void**)&h4lo, g_h4lo);
    cudaGetSymbolAddress((void**)&w1hi, g_w1hi);  cudaGetSymbolAddress((void**)&w1lo, g_w1lo);
    cudaGetSymbolAddress((void**)&w2hi, g_w2hi);  cudaGetSymbolAddress((void**)&w2lo, g_w2lo);
    cudaGetSymbolAddress((void**)&w3hi, g_w3hi);  cudaGetSymbolAddress((void**)&w3lo, g_w3lo);
    cudaGetSymbolAddress((void**)&wlhi, g_wlhi);  cudaGetSymbolAddress((void**)&wllo, g_wllo);
    cudaGetSymbolAddress((void**)&wt0,  g_wt0);

    // ---- fused weight prep (1 launch) ----
    {
        const int total = 864 + 64 * 288 + 128 * 576 + 128 * 1152 + 256 * 128;
        prep_weights<<<(total + 255) / 256, 256>>>(W0, wt0, W1, w1hi, w1lo,
                                                   W2, w2hi, w2lo, W3, w3hi, w3lo,
                                                   Wl, wlhi, wllo);
    }

    const int* sp0 = sp + 0 * NVERT * SP;
    const int* sp1 = sp + 1 * NVERT * SP;
    const int* sp2 = sp + 2 * NVERT * SP;
    const int* sp3 = sp + 3 * NVERT * SP;

    const int grid4 = (NVERT + 3) / 4;   // 1256
    const int grid2 = (NVERT + 1) / 2;   // 2512

    // ---- Layer 0 (SIMT) ----
    {
        constexpr int smb = (128 * 28 + 27 * 32) * 4 + 64 * 4;
        layer0_kernel<<<grid4, 128, smb>>>(x, sp0, wt0, b0, h1hi, h1lo);
    }
    // ---- Layer 1: 32 -> 64, K=288, bf16 3-pass in, fp16 out, M=128 ----
    {
        auto k = mma_layer<32, 64, 288, 4, 4, 2, 3, true, false, 1>;
        constexpr int smb = 2048 + 3 * 2 * (128 * 64) + 3 * 2 * (64 * 64);   // 75776
        cudaFuncSetAttribute((const void*)k, cudaFuncAttributeMaxDynamicSharedMemorySize, smb);
        k<<<grid4, 256, smb>>>((const uint16_t*)h1hi, (const uint16_t*)h1lo, sp1,
                               (const uint16_t*)w1hi, (const uint16_t*)w1lo, b1,
                               h2, nullptr);
    }
    // ---- Layer 2: 64 -> 128, K=576, fp16 2-pass, fp16 out, M=64, 4 CTA/SM ----
    {
        auto k = mma_layer<64, 128, 576, 2, 1, 4, 2, true, true, 1>;
        constexpr int smb = 2048 + 2 * 1 * (64 * 64) + 2 * 2 * (128 * 64);   // 43008
        cudaFuncSetAttribute((const void*)k, cudaFuncAttributeMaxDynamicSharedMemorySize, smb);
        k<<<grid2, 128, smb>>>((const uint16_t*)h2, nullptr, sp2,
                               (const uint16_t*)w2hi, (const uint16_t*)w2lo, b2,
                               h3, nullptr);
    }
    // ---- Layer 3: 128 -> 128, K=1152, fp16 2-pass, bf16 hi/lo out, M=64 ----
    {
        auto k = mma_layer<128, 128, 1152, 2, 1, 4, 2, true, true, 0>;
        constexpr int smb = 2048 + 2 * 1 * (64 * 64) + 2 * 2 * (128 * 64);   // 43008
        cudaFuncSetAttribute((const void*)k, cudaFuncAttributeMaxDynamicSharedMemorySize, smb);
        k<<<grid2, 128, smb>>>((const uint16_t*)h3, nullptr, sp3,
                               (const uint16_t*)w3hi, (const uint16_t*)w3lo, b3,
                               h4hi, h4lo);
    }
    // ---- Final: 128 -> 256, no gather, bf16 3-pass, f32 out, M=64 ----
    {
        auto k = mma_layer<128, 256, 128, 2, 2, 4, 2, false, false, 2>;
        constexpr int smb = 2048 + 2 * 2 * (64 * 64) + 2 * 2 * (256 * 64);   // 83968
        cudaFuncSetAttribute((const void*)k, cudaFuncAttributeMaxDynamicSharedMemorySize, smb);
        k<<<grid2, 256, smb>>>((const uint16_t*)h4hi, (const uint16_t*)h4lo, nullptr,
                               (const uint16_t*)wlhi, (const uint16_t*)wllo, bl,
                               out, nullptr);
    }
}

// round 12
// speedup vs baseline: 1.9693x; 1.0920x over previous
#include <cuda_runtime.h>
#include <cuda_bf16.h>
#include <cuda_fp16.h>
#include <cstdint>
#include <cstddef>

static constexpr int BATCH = 32;
static constexpr int NVERT = 5023;
static constexpr int SP    = 9;

// ---------------------------------------------------------------------------
// Helpers (sm_100 base target: mma.sync + ldmatrix + cp.async only)
// ---------------------------------------------------------------------------
__device__ __forceinline__ uint32_t smem_u32(const void* p) {
    uint32_t a;
    asm("{ .reg .u64 t; cvta.to.shared.u64 t, %1; cvt.u32.u64 %0, t; }" : "=r"(a) : "l"(p));
    return a;
}
__device__ __forceinline__ void cp16(uint32_t dst, const void* src, int srcbytes) {
    asm volatile("cp.async.cg.shared.global [%0], [%1], 16, %2;"
                 :: "r"(dst), "l"(src), "r"(srcbytes));
}
__device__ __forceinline__ void cp_commit() {
    asm volatile("cp.async.commit_group;" ::: "memory");
}
template<int N> __device__ __forceinline__ void cp_wait() {
    if constexpr (N == 0) asm volatile("cp.async.wait_group 0;" ::: "memory");
    else if constexpr (N == 1) asm volatile("cp.async.wait_group 1;" ::: "memory");
    else asm volatile("cp.async.wait_group 2;" ::: "memory");
}
__device__ __forceinline__ void ldm4(uint32_t addr, uint32_t* r) {
    asm volatile("ldmatrix.sync.aligned.m8n8.x4.shared.b16 {%0,%1,%2,%3}, [%4];"
                 : "=r"(r[0]), "=r"(r[1]), "=r"(r[2]), "=r"(r[3]) : "r"(addr));
}
__device__ __forceinline__ void mma_fp16(float* d, const uint32_t* a, const uint32_t* b) {
    asm volatile("mma.sync.aligned.m16n8k16.row.col.f32.f16.f16.f32 "
                 "{%0,%1,%2,%3}, {%4,%5,%6,%7}, {%8,%9}, {%0,%1,%2,%3};"
                 : "+f"(d[0]), "+f"(d[1]), "+f"(d[2]), "+f"(d[3])
                 : "r"(a[0]), "r"(a[1]), "r"(a[2]), "r"(a[3]), "r"(b[0]), "r"(b[1]));
}
// SW64 swizzle for 64-byte rows (8 rows x 64B atom = 512B)
__device__ __forceinline__ uint32_t swz64(uint32_t off) { return off ^ ((off >> 3) & 0x30); }

// ---------------------------------------------------------------------------
// Device global scratch — all activations are single fp16 planes now.
// ---------------------------------------------------------------------------
__device__ __half g_h1[(size_t)BATCH * NVERT * 32];
__device__ __half g_h2[(size_t)BATCH * NVERT * 64];
__device__ __half g_h3[(size_t)BATCH * NVERT * 128];
__device__ __half g_h4[(size_t)BATCH * NVERT * 128];

__device__ float  g_wt0[27 * 32];
__device__ __half g_w1hi[64 * 288],   g_w1lo[64 * 288];
__device__ __half g_w2hi[128 * 576],  g_w2lo[128 * 576];
__device__ __half g_w3hi[128 * 1152], g_w3lo[128 * 1152];
__device__ __half g_wlhi[256 * 128],  g_wllo[256 * 128];

// ---------------------------------------------------------------------------
// Fused weight-prep kernel: W0 transpose + fp16 hi/lo split for W1..W3, Wl
// ---------------------------------------------------------------------------
__global__ void prep_weights(const float* W0, float* wt0,
                             const float* W1, __half* w1hi, __half* w1lo,
                             const float* W2, __half* w2hi, __half* w2lo,
                             const float* W3, __half* w3hi, __half* w3lo,
                             const float* Wl, __half* wlhi, __half* wllo) {
    int t = blockIdx.x * blockDim.x + threadIdx.x;
    if (t < 864) {
        int k = t / 32, o = t - k * 32;
        wt0[t] = W0[o * 27 + k];
        return;
    }
    t -= 864;
    const float* W; __half* hi; __half* lo;
    if (t < 64 * 288)                       { W = W1; hi = w1hi; lo = w1lo; }
    else if ((t -= 64 * 288)  < 128 * 576)  { W = W2; hi = w2hi; lo = w2lo; }
    else if ((t -= 128 * 576) < 128 * 1152) { W = W3; hi = w3hi; lo = w3lo; }
    else if ((t -= 128 * 1152) < 256 * 128) { W = Wl; hi = wlhi; lo = wllo; }
    else return;
    float w = W[t];
    __half h = __float2half_rn(w);
    hi[t] = h;
    lo[t] = __float2half_rn(w - __half2float(h));
}

// ---------------------------------------------------------------------------
// Layer 0 (SIMT fp32, tiny): 3 -> 32, emits a single fp16 plane
// ---------------------------------------------------------------------------
__global__ void __launch_bounds__(128)
layer0_kernel(const float* __restrict__ x,
              const int*   __restrict__ sidx_g,
              const float* __restrict__ Wt,
              const float* __restrict__ bias,
              __half* __restrict__ hout) {
    constexpr int IN_C = 3, OUT_C = 32, KC = 27, ROWS = 128, TM = 8, TN = 4;
    constexpr int TX = OUT_C / TN;
    constexpr int NT = 128;
    constexpr int AS = KC + 1;

    extern __shared__ __align__(1024) char dsm[];
    float* Asm = (float*)dsm;
    float* Wsm = Asm + ROWS * AS;
    int*   sidx = (int*)(Wsm + KC * OUT_C);

    const int tid = threadIdx.x;
    const int tx = tid % TX, ty = tid / TX;
    const int v0 = blockIdx.x * 4;

    if (tid < 36) {
        int vt = tid / SP, s = tid - vt * SP;
        int v = v0 + vt; if (v >= NVERT) v = NVERT - 1;
        sidx[tid] = sidx_g[v * SP + s];
    }
    for (int t = tid; t < KC * OUT_C; t += NT) Wsm[t] = Wt[t];
    __syncthreads();
    for (int t = tid; t < ROWS * KC; t += NT) {
        int r = t / KC, kk = t - r * KC;
        int vt = r >> 5, b = r & 31;
        int s = kk / IN_C, c = kk - s * IN_C;
        int srow = sidx[vt * SP + s];
        Asm[r * AS + kk] = x[((size_t)b * NVERT + srow) * IN_C + c];
    }
    __syncthreads();

    float acc[TM][TN];
#pragma unroll
    for (int i = 0; i < TM; ++i)
#pragma unroll
        for (int j = 0; j < TN; ++j) acc[i][j] = 0.f;

#pragma unroll
    for (int k = 0; k < KC; ++k) {
        float a[TM];
#pragma unroll
        for (int i = 0; i < TM; ++i) a[i] = Asm[(ty * TM + i) * AS + k];
        float4 wv = *(const float4*)(Wsm + k * OUT_C + tx * TN);
        float w[TN] = {wv.x, wv.y, wv.z, wv.w};
#pragma unroll
        for (int i = 0; i < TM; ++i)
#pragma unroll
            for (int j = 0; j < TN; ++j) acc[i][j] += a[i] * w[j];
    }

#pragma unroll
    for (int i = 0; i < TM; ++i) {
        int r = ty * TM + i;
        int vt = r >> 5, b = r & 31;
        int v = v0 + vt;
        if (v < NVERT) {
            size_t off = ((size_t)b * NVERT + v) * OUT_C + tx * TN;
#pragma unroll
            for (int j = 0; j < TN; ++j) {
                float y = acc[i][j] + __ldg(&bias[tx * TN + j]);
                hout[off + j] = __float2half_rn(y);
            }
        }
    }
}

// ---------------------------------------------------------------------------
// HMMA fp16 2-pass layer: A is one fp16 plane, W is fp16 hi/lo.
//   D = A*Whi + A*Wlo  (= A * W_fp32-exact), fp32 accumulators.
//   OUTMODE: 1 = fp16 single plane, 2 = f32 final.
// NT = 32*WRG*WCG threads; max-blocks 512/NT. KC=32, NSTAGE-deep cp.async
// pipeline, prefetch ISSUED BEFORE the wait; two NT-thread barriers per chunk.
// smem header: [0,256) sidx, [256,1280) bias, [2048...) tiles.
// ---------------------------------------------------------------------------
template<int IN_C, int OUT_C, int KPAD, int MV, int WRG, int WCG,
         int NSTAGE, bool GATHER, int OUTMODE>
__global__ void __launch_bounds__(32 * WRG * WCG, 512 / (32 * WRG * WCG))
mma_layer(const __half* __restrict__ hin,
          const int*    __restrict__ sidx_g,
          const __half* __restrict__ whi,
          const __half* __restrict__ wlo,
          const float*  __restrict__ bias,
          void*         __restrict__ outp) {
    constexpr int NT    = 32 * WRG * WCG;
    constexpr int MROWS = MV * 32;
    constexpr int NCH   = KPAD / 32;
    constexpr int ATB   = MROWS * 64;           // bytes per A stage (one plane)
    constexpr int BTB   = OUT_C * 64;           // bytes per B plane-buffer
    constexpr int SM_A  = 2048;                 // after sidx [0,256) + bias [256,1280)
    constexpr int SM_B  = SM_A + NSTAGE * ATB;
    constexpr int WARP_R = MROWS / WRG;
    constexpr int WARP_C = OUT_C / WCG;
    constexpr int RS = WARP_R / 16;
    constexpr int NO = WARP_C / 8;
    constexpr int TOT_A = MROWS * 4;            // 16B tasks per chunk
    constexpr int TOT_B = OUT_C * 4 * 2;

    extern __shared__ __align__(1024) char dsm[];
    const uint32_t sbase = smem_u32(dsm);
    int*   sidx = (int*)dsm;
    float* bsm  = (float*)(dsm + 256);

    const int tid  = threadIdx.x;
    const int wid  = tid >> 5;
    const int lane = tid & 31;
    const int v0   = blockIdx.x * MV;

    const int wr = wid % WRG, wc = wid / WRG;
    const int warp_r0 = wr * WARP_R;
    const int warp_c0 = wc * WARP_C;

    if (GATHER && tid < MV * SP) {
        int vt = tid / SP, s = tid - vt * SP;
        int v = v0 + vt; if (v >= NVERT) v = NVERT - 1;
        sidx[tid] = sidx_g[v * SP + s];
    }
    for (int t = tid; t < OUT_C; t += NT) bsm[t] = bias[t];
    __syncthreads();

    // ---- chunk loader into pipeline stage st ----
    auto load_chunk = [&](int ch, int st) {
#pragma unroll
        for (int t = tid; t < TOT_A; t += NT) {
            int r = t >> 2, g = t & 3;
            int vt = r >> 5, b = r & 31;
            int kg = ch * 32 + g * 8;
            int s = GATHER ? kg / IN_C : 0;
            int c = GATHER ? kg - s * IN_C : kg;
            int v = v0 + vt; if (v >= NVERT) v = NVERT - 1;
            int srow = GATHER ? sidx[vt * SP + s] : v;
            const __half* src = hin + ((size_t)b * NVERT + srow) * IN_C + c;
            uint32_t dst = sbase + SM_A + (uint32_t)st * ATB
                         + swz64((uint32_t)(r * 64 + g * 16));
            cp16(dst, src, 16);
        }
#pragma unroll
        for (int t = tid; t < TOT_B; t += NT) {
            int plane = t >= OUT_C * 4;
            int rg = plane ? t - OUT_C * 4 : t;
            int n = rg >> 2, g = rg & 3;
            int kg = ch * 32 + g * 8;
            const __half* src = (plane ? wlo : whi) + (size_t)n * KPAD + kg;
            uint32_t dst = sbase + SM_B + (uint32_t)(st * 2 + plane) * BTB
                         + swz64((uint32_t)(n * 64 + g * 16));
            cp16(dst, src, 16);
        }
        cp_commit();
    };

    float acc[RS][NO][4];
#pragma unroll
    for (int i = 0; i < RS; ++i)
#pragma unroll
        for (int j = 0; j < NO; ++j)
#pragma unroll
            for (int q = 0; q < 4; ++q) acc[i][j][q] = 0.f;

    const int grp = lane >> 3, lr = lane & 7;

#pragma unroll
    for (int i = 0; i < NSTAGE - 1; ++i) load_chunk(i, i);

    for (int ch = 0; ch < NCH; ++ch) {
        const int st = ch % NSTAGE;

        // issue prefetch BEFORE waiting (overlap addr math + cp issue)
        if (ch + NSTAGE - 1 < NCH) load_chunk(ch + NSTAGE - 1, (ch + NSTAGE - 1) % NSTAGE);
        else                       cp_commit();

        cp_wait<NSTAGE - 1>();
        __syncthreads();

        const uint32_t A_  = sbase + SM_A + (uint32_t)st * ATB;
        const uint32_t Bhi = sbase + SM_B + (uint32_t)(st * 2 + 0) * BTB;
        const uint32_t Blo = sbase + SM_B + (uint32_t)(st * 2 + 1) * BTB;

#pragma unroll
        for (int ks = 0; ks < 2; ++ks) {
            uint32_t bh[NO][2], bl_[NO][2];
#pragma unroll
            for (int p16 = 0; p16 < NO / 2; ++p16) {
                int n  = warp_c0 + p16 * 16 + (grp >> 1) * 8 + lr;
                int c16 = ks * 2 + (grp & 1);
                uint32_t off = swz64((uint32_t)(n * 64 + c16 * 16));
                uint32_t m[4];
                ldm4(Bhi + off, m);
                bh[2 * p16][0] = m[0]; bh[2 * p16][1] = m[1];
                bh[2 * p16 + 1][0] = m[2]; bh[2 * p16 + 1][1] = m[3];
                ldm4(Blo + off, m);
                bl_[2 * p16][0] = m[0]; bl_[2 * p16][1] = m[1];
                bl_[2 * p16 + 1][0] = m[2]; bl_[2 * p16 + 1][1] = m[3];
            }
#pragma unroll
            for (int sub = 0; sub < RS; ++sub) {
                int row = warp_r0 + sub * 16 + (grp & 1) * 8 + lr;
                int c16 = ks * 2 + (grp >> 1);
                uint32_t off = swz64((uint32_t)(row * 64 + c16 * 16));
                uint32_t ah[4];
                ldm4(A_ + off, ah);
#pragma unroll
                for (int oct = 0; oct < NO; ++oct) {
                    mma_fp16(acc[sub][oct], ah, bh[oct]);
                    mma_fp16(acc[sub][oct], ah, bl_[oct]);
                }
            }
        }
        __syncthreads();
    }

    // ---- epilogue: bias + store per OUTMODE ----
    const int tq = lane >> 2, tr = lane & 3;
#pragma unroll
    for (int sub = 0; sub < RS; ++sub) {
#pragma unroll
        for (int half = 0; half < 2; ++half) {
            int r = warp_r0 + sub * 16 + half * 8 + tq;
            int vt = r >> 5, b = r & 31;
            int v = v0 + vt;
            if (v >= NVERT) continue;
#pragma unroll
            for (int oct = 0; oct < NO; ++oct) {
                int col = warp_c0 + oct * 8 + tr * 2;
                float y0 = acc[sub][oct][2 * half]     + bsm[col];
                float y1 = acc[sub][oct][2 * half + 1] + bsm[col + 1];
                size_t base = ((size_t)b * NVERT + v) * OUT_C + col;
                if constexpr (OUTMODE == 2) {
                    *(float2*)((float*)outp + base) = make_float2(y0, y1);
                } else {
                    __half2 hp = __floats2half2_rn(y0, y1);
                    *(uint32_t*)((__half*)outp + base) = *reinterpret_cast<uint32_t*>(&hp);
                }
            }
        }
    }
}

// ---------------------------------------------------------------------------
// Host
// ---------------------------------------------------------------------------
extern "C" void kernel_launch(void* const* d_in, const int* in_sizes, int n_in,
                              void* d_out, int out_size) {
    const float* x  = (const float*)d_in[0];
    const int*   sp = (const int*)  d_in[1];
    const float* W0 = (const float*)d_in[2];
    const float* b0 = (const float*)d_in[3];
    const float* W1 = (const float*)d_in[4];
    const float* b1 = (const float*)d_in[5];
    const float* W2 = (const float*)d_in[6];
    const float* b2 = (const float*)d_in[7];
    const float* W3 = (const float*)d_in[8];
    const float* b3 = (const float*)d_in[9];
    const float* Wl = (const float*)d_in[10];
    const float* bl = (const float*)d_in[11];
    float* out = (float*)d_out;

    __half *h1, *h2, *h3, *h4;
    __half *w1hi, *w1lo, *w2hi, *w2lo, *w3hi, *w3lo, *wlhi, *wllo;
    float *wt0;
    cudaGetSymbolAddress((void**)&h1, g_h1);
    cudaGetSymbolAddress((void**)&h2, g_h2);
    cudaGetSymbolAddress((void**)&h3, g_h3);
    cudaGetSymbolAddress((void**)&h4, g_h4);
    cudaGetSymbolAddress((void**)&w1hi, g_w1hi);  cudaGetSymbolAddress((void**)&w1lo, g_w1lo);
    cudaGetSymbolAddress((void**)&w2hi, g_w2hi);  cudaGetSymbolAddress((void**)&w2lo, g_w2lo);
    cudaGetSymbolAddress((void**)&w3hi, g_w3hi);  cudaGetSymbolAddress((void**)&w3lo, g_w3lo);
    cudaGetSymbolAddress((void**)&wlhi, g_wlhi);  cudaGetSymbolAddress((void**)&wllo, g_wllo);
    cudaGetSymbolAddress((void**)&wt0,  g_wt0);

    // ---- fused weight prep (1 launch) ----
    {
        const int total = 864 + 64 * 288 + 128 * 576 + 128 * 1152 + 256 * 128;
        prep_weights<<<(total + 255) / 256, 256>>>(W0, wt0, W1, w1hi, w1lo,
                                                   W2, w2hi, w2lo, W3, w3hi, w3lo,
                                                   Wl, wlhi, wllo);
    }

    const int* sp0 = sp + 0 * NVERT * SP;
    const int* sp1 = sp + 1 * NVERT * SP;
    const int* sp2 = sp + 2 * NVERT * SP;
    const int* sp3 = sp + 3 * NVERT * SP;

    const int grid4 = (NVERT + 3) / 4;   // 1256
    const int grid2 = (NVERT + 1) / 2;   // 2512

    // ---- Layer 0 (SIMT, fp32 math, fp16 out) ----
    {
        constexpr int smb = (128 * 28 + 27 * 32) * 4 + 64 * 4;
        layer0_kernel<<<grid4, 128, smb>>>(x, sp0, wt0, b0, h1);
    }
    // ---- Layer 1: 32 -> 64, K=288, M=128, 256 thr, 3-stage ----
    {
        auto k = mma_layer<32, 64, 288, 4, 4, 2, 3, true, 1>;
        constexpr int smb = 2048 + 3 * (128 * 64) + 3 * 2 * (64 * 64);   // 51200
        cudaFuncSetAttribute((const void*)k, cudaFuncAttributeMaxDynamicSharedMemorySize, smb);
        k<<<grid4, 256, smb>>>(h1, sp1, w1hi, w1lo, b1, h2);
    }
    // ---- Layer 2: 64 -> 128, K=576, M=64, 128 thr (4 CTA/SM), 2-stage ----
    {
        auto k = mma_layer<64, 128, 576, 2, 1, 4, 2, true, 1>;
        constexpr int smb = 2048 + 2 * (64 * 64) + 2 * 2 * (128 * 64);   // 43008
        cudaFuncSetAttribute((const void*)k, cudaFuncAttributeMaxDynamicSharedMemorySize, smb);
        k<<<grid2, 128, smb>>>(h2, sp2, w2hi, w2lo, b2, h3);
    }
    // ---- Layer 3: 128 -> 128, K=1152, M=64, 128 thr (4 CTA/SM), 2-stage ----
    {
        auto k = mma_layer<128, 128, 1152, 2, 1, 4, 2, true, 1>;
        constexpr int smb = 2048 + 2 * (64 * 64) + 2 * 2 * (128 * 64);   // 43008
        cudaFuncSetAttribute((const void*)k, cudaFuncAttributeMaxDynamicSharedMemorySize, smb);
        k<<<grid2, 128, smb>>>(h3, sp3, w3hi, w3lo, b3, h4);
    }
    // ---- Final: 128 -> 256, no gather, M=64, 256 thr, 2-stage, f32 out ----
    {
        auto k = mma_layer<128, 256, 128, 2, 2, 4, 2, false, 2>;
        constexpr int smb = 2048 + 2 * (64 * 64) + 2 * 2 * (256 * 64);   // 75776
        cudaFuncSetAttribute((const void*)k, cudaFuncAttributeMaxDynamicSharedMemorySize, smb);
        k<<<grid2, 256, smb>>>(h4, nullptr, wlhi, wllo, bl, out);
    }
}

// round 13
// speedup vs baseline: 3.0957x; 1.5720x over previous
#include <cuda_runtime.h>
#include <cuda_bf16.h>
#include <cuda_fp16.h>
#include <cstdint>
#include <cstddef>

static constexpr int BATCH = 32;
static constexpr int NVERT = 5023;
static constexpr int SP    = 9;

// ---------------------------------------------------------------------------
// Helpers (sm_100 base target: mma.sync + ldmatrix + cp.async only)
// ---------------------------------------------------------------------------
__device__ __forceinline__ uint32_t smem_u32(const void* p) {
    uint32_t a;
    asm("{ .reg .u64 t; cvta.to.shared.u64 t, %1; cvt.u32.u64 %0, t; }" : "=r"(a) : "l"(p));
    return a;
}
__device__ __forceinline__ void cp16(uint32_t dst, const void* src, int srcbytes) {
    asm volatile("cp.async.cg.shared.global [%0], [%1], 16, %2;"
                 :: "r"(dst), "l"(src), "r"(srcbytes));
}
__device__ __forceinline__ void cp_commit() {
    asm volatile("cp.async.commit_group;" ::: "memory");
}
template<int N> __device__ __forceinline__ void cp_wait() {
    if constexpr (N == 0) asm volatile("cp.async.wait_group 0;" ::: "memory");
    else if constexpr (N == 1) asm volatile("cp.async.wait_group 1;" ::: "memory");
    else asm volatile("cp.async.wait_group 2;" ::: "memory");
}
__device__ __forceinline__ void ldm4(uint32_t addr, uint32_t* r) {
    asm volatile("ldmatrix.sync.aligned.m8n8.x4.shared.b16 {%0,%1,%2,%3}, [%4];"
                 : "=r"(r[0]), "=r"(r[1]), "=r"(r[2]), "=r"(r[3]) : "r"(addr));
}
__device__ __forceinline__ void mma_fp16(float* d, const uint32_t* a, const uint32_t* b) {
    asm volatile("mma.sync.aligned.m16n8k16.row.col.f32.f16.f16.f32 "
                 "{%0,%1,%2,%3}, {%4,%5,%6,%7}, {%8,%9}, {%0,%1,%2,%3};"
                 : "+f"(d[0]), "+f"(d[1]), "+f"(d[2]), "+f"(d[3])
                 : "r"(a[0]), "r"(a[1]), "r"(a[2]), "r"(a[3]), "r"(b[0]), "r"(b[1]));
}
// SW64 swizzle for 64-byte rows (8 rows x 64B atom = 512B)
__device__ __forceinline__ uint32_t swz64(uint32_t off) { return off ^ ((off >> 3) & 0x30); }

// ---------------------------------------------------------------------------
// Device global scratch — fp16 activations, fp16 weights (single plane each)
// ---------------------------------------------------------------------------
__device__ __half g_h1[(size_t)BATCH * NVERT * 32];
__device__ __half g_h2[(size_t)BATCH * NVERT * 64];
__device__ __half g_h3[(size_t)BATCH * NVERT * 128];
__device__ __half g_h4[(size_t)BATCH * NVERT * 128];

__device__ float  g_wt0[27 * 32];
__device__ __half g_w1[64 * 288];
__device__ __half g_w2[128 * 576];
__device__ __half g_w3[128 * 1152];
__device__ __half g_wl[256 * 128];

// ---------------------------------------------------------------------------
// Fused weight-prep kernel: W0 transpose + fp16 convert for W1..W3, Wl
// ---------------------------------------------------------------------------
__global__ void prep_weights(const float* W0, float* wt0,
                             const float* W1, __half* w1,
                             const float* W2, __half* w2,
                             const float* W3, __half* w3,
                             const float* Wl, __half* wl) {
    int t = blockIdx.x * blockDim.x + threadIdx.x;
    if (t < 864) {
        int k = t / 32, o = t - k * 32;
        wt0[t] = W0[o * 27 + k];
        return;
    }
    t -= 864;
    const float* W; __half* dst;
    if (t < 64 * 288)                       { W = W1; dst = w1; }
    else if ((t -= 64 * 288)  < 128 * 576)  { W = W2; dst = w2; }
    else if ((t -= 128 * 576) < 128 * 1152) { W = W3; dst = w3; }
    else if ((t -= 128 * 1152) < 256 * 128) { W = Wl; dst = wl; }
    else return;
    dst[t] = __float2half_rn(W[t]);
}

// ---------------------------------------------------------------------------
// Layer 0 (SIMT fp32, tiny): 3 -> 32, emits a single fp16 plane
// ---------------------------------------------------------------------------
__global__ void __launch_bounds__(128)
layer0_kernel(const float* __restrict__ x,
              const int*   __restrict__ sidx_g,
              const float* __restrict__ Wt,
              const float* __restrict__ bias,
              __half* __restrict__ hout) {
    constexpr int IN_C = 3, OUT_C = 32, KC = 27, ROWS = 128, TM = 8, TN = 4;
    constexpr int TX = OUT_C / TN;
    constexpr int NT = 128;
    constexpr int AS = KC + 1;

    extern __shared__ __align__(1024) char dsm[];
    float* Asm = (float*)dsm;
    float* Wsm = Asm + ROWS * AS;
    int*   sidx = (int*)(Wsm + KC * OUT_C);

    const int tid = threadIdx.x;
    const int tx = tid % TX, ty = tid / TX;
    const int v0 = blockIdx.x * 4;

    if (tid < 36) {
        int vt = tid / SP, s = tid - vt * SP;
        int v = v0 + vt; if (v >= NVERT) v = NVERT - 1;
        sidx[tid] = sidx_g[v * SP + s];
    }
    for (int t = tid; t < KC * OUT_C; t += NT) Wsm[t] = Wt[t];
    __syncthreads();
    for (int t = tid; t < ROWS * KC; t += NT) {
        int r = t / KC, kk = t - r * KC;
        int vt = r >> 5, b = r & 31;
        int s = kk / IN_C, c = kk - s * IN_C;
        int srow = sidx[vt * SP + s];
        Asm[r * AS + kk] = x[((size_t)b * NVERT + srow) * IN_C + c];
    }
    __syncthreads();

    float acc[TM][TN];
#pragma unroll
    for (int i = 0; i < TM; ++i)
#pragma unroll
        for (int j = 0; j < TN; ++j) acc[i][j] = 0.f;

#pragma unroll
    for (int k = 0; k < KC; ++k) {
        float a[TM];
#pragma unroll
        for (int i = 0; i < TM; ++i) a[i] = Asm[(ty * TM + i) * AS + k];
        float4 wv = *(const float4*)(Wsm + k * OUT_C + tx * TN);
        float w[TN] = {wv.x, wv.y, wv.z, wv.w};
#pragma unroll
        for (int i = 0; i < TM; ++i)
#pragma unroll
            for (int j = 0; j < TN; ++j) acc[i][j] += a[i] * w[j];
    }

#pragma unroll
    for (int i = 0; i < TM; ++i) {
        int r = ty * TM + i;
        int vt = r >> 5, b = r & 31;
        int v = v0 + vt;
        if (v < NVERT) {
            size_t off = ((size_t)b * NVERT + v) * OUT_C + tx * TN;
#pragma unroll
            for (int j = 0; j < TN; ++j) {
                float y = acc[i][j] + __ldg(&bias[tx * TN + j]);
                hout[off + j] = __float2half_rn(y);
            }
        }
    }
}

// ---------------------------------------------------------------------------
// HMMA fp16 single-pass layer: A fp16 plane, W fp16 plane, fp32 accumulators.
//   OUTMODE: 1 = fp16 single plane, 2 = f32 final.
// NT = 32*WRG*WCG threads; max-blocks 512/NT. KC=32, NSTAGE-deep cp.async
// pipeline, prefetch ISSUED BEFORE the wait; two NT-thread barriers per chunk.
// smem header: [0,256) sidx, [256,1280) bias, [2048...) tiles.
// ---------------------------------------------------------------------------
template<int IN_C, int OUT_C, int KPAD, int MV, int WRG, int WCG,
         int NSTAGE, bool GATHER, int OUTMODE>
__global__ void __launch_bounds__(32 * WRG * WCG, 512 / (32 * WRG * WCG))
mma_layer(const __half* __restrict__ hin,
          const int*    __restrict__ sidx_g,
          const __half* __restrict__ w,
          const float*  __restrict__ bias,
          void*         __restrict__ outp) {
    constexpr int NT    = 32 * WRG * WCG;
    constexpr int MROWS = MV * 32;
    constexpr int NCH   = KPAD / 32;
    constexpr int ATB   = MROWS * 64;           // bytes per A stage
    constexpr int BTB   = OUT_C * 64;           // bytes per B stage (one plane)
    constexpr int SM_A  = 2048;                 // after sidx [0,256) + bias [256,1280)
    constexpr int SM_B  = SM_A + NSTAGE * ATB;
    constexpr int WARP_R = MROWS / WRG;
    constexpr int WARP_C = OUT_C / WCG;
    constexpr int RS = WARP_R / 16;
    constexpr int NO = WARP_C / 8;
    constexpr int TOT_A = MROWS * 4;            // 16B tasks per chunk
    constexpr int TOT_B = OUT_C * 4;

    extern __shared__ __align__(1024) char dsm[];
    const uint32_t sbase = smem_u32(dsm);
    int*   sidx = (int*)dsm;
    float* bsm  = (float*)(dsm + 256);

    const int tid  = threadIdx.x;
    const int wid  = tid >> 5;
    const int lane = tid & 31;
    const int v0   = blockIdx.x * MV;

    const int wr = wid % WRG, wc = wid / WRG;
    const int warp_r0 = wr * WARP_R;
    const int warp_c0 = wc * WARP_C;

    if (GATHER && tid < MV * SP) {
        int vt = tid / SP, s = tid - vt * SP;
        int v = v0 + vt; if (v >= NVERT) v = NVERT - 1;
        sidx[tid] = sidx_g[v * SP + s];
    }
    for (int t = tid; t < OUT_C; t += NT) bsm[t] = bias[t];
    __syncthreads();

    // ---- chunk loader into pipeline stage st ----
    auto load_chunk = [&](int ch, int st) {
#pragma unroll
        for (int t = tid; t < TOT_A; t += NT) {
            int r = t >> 2, g = t & 3;
            int vt = r >> 5, b = r & 31;
            int kg = ch * 32 + g * 8;
            int s = GATHER ? kg / IN_C : 0;
            int c = GATHER ? kg - s * IN_C : kg;
            int v = v0 + vt; if (v >= NVERT) v = NVERT - 1;
            int srow = GATHER ? sidx[vt * SP + s] : v;
            const __half* src = hin + ((size_t)b * NVERT + srow) * IN_C + c;
            uint32_t dst = sbase + SM_A + (uint32_t)st * ATB
                         + swz64((uint32_t)(r * 64 + g * 16));
            cp16(dst, src, 16);
        }
#pragma unroll
        for (int t = tid; t < TOT_B; t += NT) {
            int n = t >> 2, g = t & 3;
            int kg = ch * 32 + g * 8;
            const __half* src = w + (size_t)n * KPAD + kg;
            uint32_t dst = sbase + SM_B + (uint32_t)st * BTB
                         + swz64((uint32_t)(n * 64 + g * 16));
            cp16(dst, src, 16);
        }
        cp_commit();
    };

    float acc[RS][NO][4];
#pragma unroll
    for (int i = 0; i < RS; ++i)
#pragma unroll
        for (int j = 0; j < NO; ++j)
#pragma unroll
            for (int q = 0; q < 4; ++q) acc[i][j][q] = 0.f;

    const int grp = lane >> 3, lr = lane & 7;

#pragma unroll
    for (int i = 0; i < NSTAGE - 1; ++i) load_chunk(i, i);

    for (int ch = 0; ch < NCH; ++ch) {
        const int st = ch % NSTAGE;

        // issue prefetch BEFORE waiting (overlap addr math + cp issue)
        if (ch + NSTAGE - 1 < NCH) load_chunk(ch + NSTAGE - 1, (ch + NSTAGE - 1) % NSTAGE);
        else                       cp_commit();

        cp_wait<NSTAGE - 1>();
        __syncthreads();

        const uint32_t A_ = sbase + SM_A + (uint32_t)st * ATB;
        const uint32_t B_ = sbase + SM_B + (uint32_t)st * BTB;

#pragma unroll
        for (int ks = 0; ks < 2; ++ks) {
            uint32_t bf[NO][2];
#pragma unroll
            for (int p16 = 0; p16 < NO / 2; ++p16) {
                int n  = warp_c0 + p16 * 16 + (grp >> 1) * 8 + lr;
                int c16 = ks * 2 + (grp & 1);
                uint32_t off = swz64((uint32_t)(n * 64 + c16 * 16));
                uint32_t m[4];
                ldm4(B_ + off, m);
                bf[2 * p16][0] = m[0]; bf[2 * p16][1] = m[1];
                bf[2 * p16 + 1][0] = m[2]; bf[2 * p16 + 1][1] = m[3];
            }
#pragma unroll
            for (int sub = 0; sub < RS; ++sub) {
                int row = warp_r0 + sub * 16 + (grp & 1) * 8 + lr;
                int c16 = ks * 2 + (grp >> 1);
                uint32_t off = swz64((uint32_t)(row * 64 + c16 * 16));
                uint32_t ah[4];
                ldm4(A_ + off, ah);
#pragma unroll
                for (int oct = 0; oct < NO; ++oct)
                    mma_fp16(acc[sub][oct], ah, bf[oct]);
            }
        }
        __syncthreads();
    }

    // ---- epilogue: bias + store per OUTMODE ----
    const int tq = lane >> 2, tr = lane & 3;
#pragma unroll
    for (int sub = 0; sub < RS; ++sub) {
#pragma unroll
        for (int half = 0; half < 2; ++half) {
            int r = warp_r0 + sub * 16 + half * 8 + tq;
            int vt = r >> 5, b = r & 31;
            int v = v0 + vt;
            if (v >= NVERT) continue;
#pragma unroll
            for (int oct = 0; oct < NO; ++oct) {
                int col = warp_c0 + oct * 8 + tr * 2;
                float y0 = acc[sub][oct][2 * half]     + bsm[col];
                float y1 = acc[sub][oct][2 * half + 1] + bsm[col + 1];
                size_t base = ((size_t)b * NVERT + v) * OUT_C + col;
                if constexpr (OUTMODE == 2) {
                    *(float2*)((float*)outp + base) = make_float2(y0, y1);
                } else {
                    __half2 hp = __floats2half2_rn(y0, y1);
                    *(uint32_t*)((__half*)outp + base) = *reinterpret_cast<uint32_t*>(&hp);
                }
            }
        }
    }
}

// ---------------------------------------------------------------------------
// Host
// ---------------------------------------------------------------------------
extern "C" void kernel_launch(void* const* d_in, const int* in_sizes, int n_in,
                              void* d_out, int out_size) {
    const float* x  = (const float*)d_in[0];
    const int*   sp = (const int*)  d_in[1];
    const float* W0 = (const float*)d_in[2];
    const float* b0 = (const float*)d_in[3];
    const float* W1 = (const float*)d_in[4];
    const float* b1 = (const float*)d_in[5];
    const float* W2 = (const float*)d_in[6];
    const float* b2 = (const float*)d_in[7];
    const float* W3 = (const float*)d_in[8];
    const float* b3 = (const float*)d_in[9];
    const float* Wl = (const float*)d_in[10];
    const float* bl = (const float*)d_in[11];
    float* out = (float*)d_out;

    __half *h1, *h2, *h3, *h4, *w1, *w2, *w3, *wl;
    float *wt0;
    cudaGetSymbolAddress((void**)&h1, g_h1);
    cudaGetSymbolAddress((void**)&h2, g_h2);
    cudaGetSymbolAddress((void**)&h3, g_h3);
    cudaGetSymbolAddress((void**)&h4, g_h4);
    cudaGetSymbolAddress((void**)&w1, g_w1);
    cudaGetSymbolAddress((void**)&w2, g_w2);
    cudaGetSymbolAddress((void**)&w3, g_w3);
    cudaGetSymbolAddress((void**)&wl, g_wl);
    cudaGetSymbolAddress((void**)&wt0, g_wt0);

    // ---- fused weight prep (1 launch) ----
    {
        const int total = 864 + 64 * 288 + 128 * 576 + 128 * 1152 + 256 * 128;
        prep_weights<<<(total + 255) / 256, 256>>>(W0, wt0, W1, w1, W2, w2,
                                                   W3, w3, Wl, wl);
    }

    const int* sp0 = sp + 0 * NVERT * SP;
    const int* sp1 = sp + 1 * NVERT * SP;
    const int* sp2 = sp + 2 * NVERT * SP;
    const int* sp3 = sp + 3 * NVERT * SP;

    const int grid4 = (NVERT + 3) / 4;   // 1256
    const int grid2 = (NVERT + 1) / 2;   // 2512

    // ---- Layer 0 (SIMT, fp32 math, fp16 out) ----
    {
        constexpr int smb = (128 * 28 + 27 * 32) * 4 + 64 * 4;
        layer0_kernel<<<grid4, 128, smb>>>(x, sp0, wt0, b0, h1);
    }
    // ---- Layer 1: 32 -> 64, K=288, M=128, 256 thr, 3-stage ----
    {
        auto k = mma_layer<32, 64, 288, 4, 4, 2, 3, true, 1>;
        constexpr int smb = 2048 + 3 * (128 * 64) + 3 * (64 * 64);   // 38912
        cudaFuncSetAttribute((const void*)k, cudaFuncAttributeMaxDynamicSharedMemorySize, smb);
        k<<<grid4, 256, smb>>>(h1, sp1, w1, b1, h2);
    }
    // ---- Layer 2: 64 -> 128, K=576, M=64, 128 thr (4 CTA/SM), 3-stage ----
    {
        auto k = mma_layer<64, 128, 576, 2, 1, 4, 3, true, 1>;
        constexpr int smb = 2048 + 3 * (64 * 64) + 3 * (128 * 64);   // 38912
        cudaFuncSetAttribute((const void*)k, cudaFuncAttributeMaxDynamicSharedMemorySize, smb);
        k<<<grid2, 128, smb>>>(h2, sp2, w2, b2, h3);
    }
    // ---- Layer 3: 128 -> 128, K=1152, M=64, 128 thr (4 CTA/SM), 3-stage ----
    {
        auto k = mma_layer<128, 128, 1152, 2, 1, 4, 3, true, 1>;
        constexpr int smb = 2048 + 3 * (64 * 64) + 3 * (128 * 64);   // 38912
        cudaFuncSetAttribute((const void*)k, cudaFuncAttributeMaxDynamicSharedMemorySize, smb);
        k<<<grid2, 128, smb>>>(h3, sp3, w3, b3, h4);
    }
    // ---- Final: 128 -> 256, no gather, M=64, 256 thr, 3-stage, f32 out ----
    {
        auto k = mma_layer<128, 256, 128, 2, 2, 4, 3, false, 2>;
        constexpr int smb = 2048 + 3 * (64 * 64) + 3 * (256 * 64);   // 63488
        cudaFuncSetAttribute((const void*)k, cudaFuncAttributeMaxDynamicSharedMemorySize, smb);
        k<<<grid2, 256, smb>>>(h4, nullptr, wl, bl, out);
    }
}

// round 16
// speedup vs baseline: 3.1311x; 1.0114x over previous
#include <cuda_runtime.h>
#include <cuda_bf16.h>
#include <cuda_fp16.h>
#include <cstdint>
#include <cstddef>

static constexpr int BATCH = 32;
static constexpr int NVERT = 5023;
static constexpr int SP    = 9;

// ---------------------------------------------------------------------------
// Helpers (sm_100 base target: mma.sync + ldmatrix + cp.async only)
// ---------------------------------------------------------------------------
__device__ __forceinline__ uint32_t smem_u32(const void* p) {
    uint32_t a;
    asm("{ .reg .u64 t; cvta.to.shared.u64 t, %1; cvt.u32.u64 %0, t; }" : "=r"(a) : "l"(p));
    return a;
}
__device__ __forceinline__ void cp16(uint32_t dst, const void* src, int srcbytes) {
    asm volatile("cp.async.cg.shared.global [%0], [%1], 16, %2;"
                 :: "r"(dst), "l"(src), "r"(srcbytes));
}
__device__ __forceinline__ void cp_commit() {
    asm volatile("cp.async.commit_group;" ::: "memory");
}
template<int N> __device__ __forceinline__ void cp_wait() {
    if constexpr (N == 0) asm volatile("cp.async.wait_group 0;" ::: "memory");
    else if constexpr (N == 1) asm volatile("cp.async.wait_group 1;" ::: "memory");
    else asm volatile("cp.async.wait_group 2;" ::: "memory");
}
__device__ __forceinline__ void ldm4(uint32_t addr, uint32_t* r) {
    asm volatile("ldmatrix.sync.aligned.m8n8.x4.shared.b16 {%0,%1,%2,%3}, [%4];"
                 : "=r"(r[0]), "=r"(r[1]), "=r"(r[2]), "=r"(r[3]) : "r"(addr));
}
__device__ __forceinline__ void mma_fp16(float* d, const uint32_t* a, const uint32_t* b) {
    asm volatile("mma.sync.aligned.m16n8k16.row.col.f32.f16.f16.f32 "
                 "{%0,%1,%2,%3}, {%4,%5,%6,%7}, {%8,%9}, {%0,%1,%2,%3};"
                 : "+f"(d[0]), "+f"(d[1]), "+f"(d[2]), "+f"(d[3])
                 : "r"(a[0]), "r"(a[1]), "r"(a[2]), "r"(a[3]), "r"(b[0]), "r"(b[1]));
}

// ---------------------------------------------------------------------------
// Device global scratch — fp16 activations, fp16 weights (single plane each)
// ---------------------------------------------------------------------------
__device__ __half g_h1[(size_t)BATCH * NVERT * 32];
__device__ __half g_h2[(size_t)BATCH * NVERT * 64];
__device__ __half g_h3[(size_t)BATCH * NVERT * 128];
__device__ __half g_h4[(size_t)BATCH * NVERT * 128];

__device__ float  g_wt0[27 * 32];
__device__ __half g_w1[64 * 288];
__device__ __half g_w2[128 * 576];
__device__ __half g_w3[128 * 1152];
__device__ __half g_wl[256 * 128];

// ---------------------------------------------------------------------------
// Fused weight-prep kernel: W0 transpose + fp16 convert for W1..W3, Wl
// ---------------------------------------------------------------------------
__global__ void prep_weights(const float* W0, float* wt0,
                             const float* W1, __half* w1,
                             const float* W2, __half* w2,
                             const float* W3, __half* w3,
                             const float* Wl, __half* wl) {
    int t = blockIdx.x * blockDim.x + threadIdx.x;
    if (t < 864) {
        int k = t / 32, o = t - k * 32;
        wt0[t] = W0[o * 27 + k];
        return;
    }
    t -= 864;
    const float* W; __half* dst;
    if (t < 64 * 288)                       { W = W1; dst = w1; }
    else if ((t -= 64 * 288)  < 128 * 576)  { W = W2; dst = w2; }
    else if ((t -= 128 * 576) < 128 * 1152) { W = W3; dst = w3; }
    else if ((t -= 128 * 1152) < 256 * 128) { W = Wl; dst = wl; }
    else return;
    dst[t] = __float2half_rn(W[t]);
}

// ---------------------------------------------------------------------------
// Layer 0 (SIMT fp32, tiny): 3 -> 32, emits a single fp16 plane
// ---------------------------------------------------------------------------
__global__ void __launch_bounds__(128)
layer0_kernel(const float* __restrict__ x,
              const int*   __restrict__ sidx_g,
              const float* __restrict__ Wt,
              const float* __restrict__ bias,
              __half* __restrict__ hout) {
    constexpr int IN_C = 3, OUT_C = 32, KC = 27, ROWS = 128, TM = 8, TN = 4;
    constexpr int TX = OUT_C / TN;
    constexpr int NT = 128;
    constexpr int AS = KC + 1;

    extern __shared__ __align__(1024) char dsm[];
    float* Asm = (float*)dsm;
    float* Wsm = Asm + ROWS * AS;
    int*   sidx = (int*)(Wsm + KC * OUT_C);

    const int tid = threadIdx.x;
    const int tx = tid % TX, ty = tid / TX;
    const int v0 = blockIdx.x * 4;

    if (tid < 36) {
        int vt = tid / SP, s = tid - vt * SP;
        int v = v0 + vt; if (v >= NVERT) v = NVERT - 1;
        sidx[tid] = sidx_g[v * SP + s];
    }
    for (int t = tid; t < KC * OUT_C; t += NT) Wsm[t] = Wt[t];
    __syncthreads();
    for (int t = tid; t < ROWS * KC; t += NT) {
        int r = t / KC, kk = t - r * KC;
        int vt = r >> 5, b = r & 31;
        int s = kk / IN_C, c = kk - s * IN_C;
        int srow = sidx[vt * SP + s];
        Asm[r * AS + kk] = x[((size_t)b * NVERT + srow) * IN_C + c];
    }
    __syncthreads();

    float acc[TM][TN];
#pragma unroll
    for (int i = 0; i < TM; ++i)
#pragma unroll
        for (int j = 0; j < TN; ++j) acc[i][j] = 0.f;

#pragma unroll
    for (int k = 0; k < KC; ++k) {
        float a[TM];
#pragma unroll
        for (int i = 0; i < TM; ++i) a[i] = Asm[(ty * TM + i) * AS + k];
        float4 wv = *(const float4*)(Wsm + k * OUT_C + tx * TN);
        float w[TN] = {wv.x, wv.y, wv.z, wv.w};
#pragma unroll
        for (int i = 0; i < TM; ++i)
#pragma unroll
            for (int j = 0; j < TN; ++j) acc[i][j] += a[i] * w[j];
    }

#pragma unroll
    for (int i = 0; i < TM; ++i) {
        int r = ty * TM + i;
        int vt = r >> 5, b = r & 31;
        int v = v0 + vt;
        if (v < NVERT) {
            size_t off = ((size_t)b * NVERT + v) * OUT_C + tx * TN;
#pragma unroll
            for (int j = 0; j < TN; ++j) {
                float y = acc[i][j] + __ldg(&bias[tx * TN + j]);
                hout[off + j] = __float2half_rn(y);
            }
        }
    }
}

// ---------------------------------------------------------------------------
// HMMA fp16 single-pass layer, parameterized K-chunk KC (32 or 64).
//   KC=32: 64B smem rows, SW64 swizzle.  KC=64: 128B rows, SW128 swizzle.
//   OUTMODE: 1 = fp16 single plane, 2 = f32 final.
// NT = 32*WRG*WCG threads; max-blocks 512/NT. NSTAGE-deep cp.async pipeline,
// prefetch ISSUED BEFORE the wait; two NT-thread barriers per chunk.
// smem header: [0,256) sidx, [256,1280) bias, [2048...) tiles.
// ---------------------------------------------------------------------------
template<int IN_C, int OUT_C, int KPAD, int KC, int MV, int WRG, int WCG,
         int NSTAGE, bool GATHER, int OUTMODE>
__global__ void __launch_bounds__(32 * WRG * WCG, 512 / (32 * WRG * WCG))
mma_layer(const __half* __restrict__ hin,
          const int*    __restrict__ sidx_g,
          const __half* __restrict__ w,
          const float*  __restrict__ bias,
          void*         __restrict__ outp) {
    constexpr int NT    = 32 * WRG * WCG;
    constexpr int MROWS = MV * 32;
    constexpr int NCH   = KPAD / KC;
    constexpr int ROWB  = KC * 2;               // smem row bytes (64 or 128)
    constexpr int UNITS = ROWB / 16;            // 16B units per row
    constexpr uint32_t SWM = (ROWB == 64) ? 0x30u : 0x70u;
    constexpr int ATB   = MROWS * ROWB;         // bytes per A stage
    constexpr int BTB   = OUT_C * ROWB;         // bytes per B stage
    constexpr int SM_A  = 2048;
    constexpr int SM_B  = SM_A + NSTAGE * ATB;
    constexpr int WARP_R = MROWS / WRG;
    constexpr int WARP_C = OUT_C / WCG;
    constexpr int RS = WARP_R / 16;
    constexpr int NO = WARP_C / 8;
    constexpr int KS = KC / 16;                 // k16 steps per chunk
    constexpr int TOT_A = MROWS * UNITS;
    constexpr int TOT_B = OUT_C * UNITS;

    extern __shared__ __align__(1024) char dsm[];
    const uint32_t sbase = smem_u32(dsm);
    int*   sidx = (int*)dsm;
    float* bsm  = (float*)(dsm + 256);

    const int tid  = threadIdx.x;
    const int wid  = tid >> 5;
    const int lane = tid & 31;
    const int v0   = blockIdx.x * MV;

    const int wr = wid % WRG, wc = wid / WRG;
    const int warp_r0 = wr * WARP_R;
    const int warp_c0 = wc * WARP_C;

    auto swz = [](uint32_t off) { return off ^ ((off >> 3) & SWM); };

    if (GATHER && tid < MV * SP) {
        int vt = tid / SP, s = tid - vt * SP;
        int v = v0 + vt; if (v >= NVERT) v = NVERT - 1;
        sidx[tid] = sidx_g[v * SP + s];
    }
    for (int t = tid; t < OUT_C; t += NT) bsm[t] = bias[t];
    __syncthreads();

    // ---- chunk loader into pipeline stage st ----
    auto load_chunk = [&](int ch, int st) {
#pragma unroll
        for (int t = tid; t < TOT_A; t += NT) {
            int r = t / UNITS, g = t % UNITS;
            int vt = r >> 5, b = r & 31;
            int kg = ch * KC + g * 8;
            int s = GATHER ? kg / IN_C : 0;
            int c = GATHER ? kg - s * IN_C : kg;
            int v = v0 + vt; if (v >= NVERT) v = NVERT - 1;
            int srow = GATHER ? sidx[vt * SP + s] : v;
            const __half* src = hin + ((size_t)b * NVERT + srow) * IN_C + c;
            uint32_t dst = sbase + SM_A + (uint32_t)st * ATB
                         + swz((uint32_t)(r * ROWB + g * 16));
            cp16(dst, src, 16);
        }
#pragma unroll
        for (int t = tid; t < TOT_B; t += NT) {
            int n = t / UNITS, g = t % UNITS;
            int kg = ch * KC + g * 8;
            const __half* src = w + (size_t)n * KPAD + kg;
            uint32_t dst = sbase + SM_B + (uint32_t)st * BTB
                         + swz((uint32_t)(n * ROWB + g * 16));
            cp16(dst, src, 16);
        }
        cp_commit();
    };

    float acc[RS][NO][4];
#pragma unroll
    for (int i = 0; i < RS; ++i)
#pragma unroll
        for (int j = 0; j < NO; ++j)
#pragma unroll
            for (int q = 0; q < 4; ++q) acc[i][j][q] = 0.f;

    const int grp = lane >> 3, lr = lane & 7;

#pragma unroll
    for (int i = 0; i < NSTAGE - 1; ++i) load_chunk(i, i);

    for (int ch = 0; ch < NCH; ++ch) {
        const int st = ch % NSTAGE;

        // issue prefetch BEFORE waiting (overlap addr math + cp issue)
        if (ch + NSTAGE - 1 < NCH) load_chunk(ch + NSTAGE - 1, (ch + NSTAGE - 1) % NSTAGE);
        else                       cp_commit();

        cp_wait<NSTAGE - 1>();
        __syncthreads();

        const uint32_t A_ = sbase + SM_A + (uint32_t)st * ATB;
        const uint32_t B_ = sbase + SM_B + (uint32_t)st * BTB;

#pragma unroll
        for (int ks = 0; ks < KS; ++ks) {
            uint32_t bf[NO][2];
#pragma unroll
            for (int p16 = 0; p16 < NO / 2; ++p16) {
                int n  = warp_c0 + p16 * 16 + (grp >> 1) * 8 + lr;
                int c16 = ks * 2 + (grp & 1);
                uint32_t off = swz((uint32_t)(n * ROWB + c16 * 16));
                uint32_t m[4];
                ldm4(B_ + off, m);
                bf[2 * p16][0] = m[0]; bf[2 * p16][1] = m[1];
                bf[2 * p16 + 1][0] = m[2]; bf[2 * p16 + 1][1] = m[3];
            }
#pragma unroll
            for (int sub = 0; sub < RS; ++sub) {
                int row = warp_r0 + sub * 16 + (grp & 1) * 8 + lr;
                int c16 = ks * 2 + (grp >> 1);
                uint32_t off = swz((uint32_t)(row * ROWB + c16 * 16));
                uint32_t ah[4];
                ldm4(A_ + off, ah);
#pragma unroll
                for (int oct = 0; oct < NO; ++oct)
                    mma_fp16(acc[sub][oct], ah, bf[oct]);
            }
        }
        __syncthreads();
    }

    // ---- epilogue: bias + store per OUTMODE ----
    const int tq = lane >> 2, tr = lane & 3;
#pragma unroll
    for (int sub = 0; sub < RS; ++sub) {
#pragma unroll
        for (int half = 0; half < 2; ++half) {
            int r = warp_r0 + sub * 16 + half * 8 + tq;
            int vt = r >> 5, b = r & 31;
            int v = v0 + vt;
            if (v >= NVERT) continue;
#pragma unroll
            for (int oct = 0; oct < NO; ++oct) {
                int col = warp_c0 + oct * 8 + tr * 2;
                float y0 = acc[sub][oct][2 * half]     + bsm[col];
                float y1 = acc[sub][oct][2 * half + 1] + bsm[col + 1];
                size_t base = ((size_t)b * NVERT + v) * OUT_C + col;
                if constexpr (OUTMODE == 2) {
                    *(float2*)((float*)outp + base) = make_float2(y0, y1);
                } else {
                    __half2 hp = __floats2half2_rn(y0, y1);
                    *(uint32_t*)((__half*)outp + base) = *reinterpret_cast<uint32_t*>(&hp);
                }
            }
        }
    }
}

// ---------------------------------------------------------------------------
// Host
// ---------------------------------------------------------------------------
extern "C" void kernel_launch(void* const* d_in, const int* in_sizes, int n_in,
                              void* d_out, int out_size) {
    const float* x  = (const float*)d_in[0];
    const int*   sp = (const int*)  d_in[1];
    const float* W0 = (const float*)d_in[2];
    const float* b0 = (const float*)d_in[3];
    const float* W1 = (const float*)d_in[4];
    const float* b1 = (const float*)d_in[5];
    const float* W2 = (const float*)d_in[6];
    const float* b2 = (const float*)d_in[7];
    const float* W3 = (const float*)d_in[8];
    const float* b3 = (const float*)d_in[9];
    const float* Wl = (const float*)d_in[10];
    const float* bl = (const float*)d_in[11];
    float* out = (float*)d_out;

    __half *h1, *h2, *h3, *h4, *w1, *w2, *w3, *wl;
    float *wt0;
    cudaGetSymbolAddress((void**)&h1, g_h1);
    cudaGetSymbolAddress((void**)&h2, g_h2);
    cudaGetSymbolAddress((void**)&h3, g_h3);
    cudaGetSymbolAddress((void**)&h4, g_h4);
    cudaGetSymbolAddress((void**)&w1, g_w1);
    cudaGetSymbolAddress((void**)&w2, g_w2);
    cudaGetSymbolAddress((void**)&w3, g_w3);
    cudaGetSymbolAddress((void**)&wl, g_wl);
    cudaGetSymbolAddress((void**)&wt0, g_wt0);

    // ---- fused weight prep (1 launch) ----
    {
        const int total = 864 + 64 * 288 + 128 * 576 + 128 * 1152 + 256 * 128;
        prep_weights<<<(total + 255) / 256, 256>>>(W0, wt0, W1, w1, W2, w2,
                                                   W3, w3, Wl, wl);
    }

    const int* sp0 = sp + 0 * NVERT * SP;
    const int* sp1 = sp + 1 * NVERT * SP;
    const int* sp2 = sp + 2 * NVERT * SP;
    const int* sp3 = sp + 3 * NVERT * SP;

    const int grid4 = (NVERT + 3) / 4;   // 1256
    const int grid2 = (NVERT + 1) / 2;   // 2512

    // ---- Layer 0 (SIMT, fp32 math, fp16 out) ----
    {
        constexpr int smb = (128 * 28 + 27 * 32) * 4 + 64 * 4;
        layer0_kernel<<<grid4, 128, smb>>>(x, sp0, wt0, b0, h1);
    }
    // ---- Layer 1: 32 -> 64, K=288, KC=32, M=128, 256 thr, 3-stage ----
    {
        auto k = mma_layer<32, 64, 288, 32, 4, 4, 2, 3, true, 1>;
        constexpr int smb = 2048 + 3 * (128 * 64) + 3 * (64 * 64);   // 38912
        cudaFuncSetAttribute((const void*)k, cudaFuncAttributeMaxDynamicSharedMemorySize, smb);
        k<<<grid4, 256, smb>>>(h1, sp1, w1, b1, h2);
    }
    // ---- Layer 2: 64 -> 128, K=576, KC=64, M=64, 128 thr (4 CTA/SM), 2-stage ----
    {
        auto k = mma_layer<64, 128, 576, 64, 2, 1, 4, 2, true, 1>;
        constexpr int smb = 2048 + 2 * (64 * 128) + 2 * (128 * 128);  // 51200
        cudaFuncSetAttribute((const void*)k, cudaFuncAttributeMaxDynamicSharedMemorySize, smb);
        k<<<grid2, 128, smb>>>(h2, sp2, w2, b2, h3);
    }
    // ---- Layer 3: 128 -> 128, K=1152, KC=64, M=64, 128 thr (4 CTA/SM), 2-stage ----
    {
        auto k = mma_layer<128, 128, 1152, 64, 2, 1, 4, 2, true, 1>;
        constexpr int smb = 2048 + 2 * (64 * 128) + 2 * (128 * 128);  // 51200
        cudaFuncSetAttribute((const void*)k, cudaFuncAttributeMaxDynamicSharedMemorySize, smb);
        k<<<grid2, 128, smb>>>(h3, sp3, w3, b3, h4);
    }
    // ---- Final: 128 -> 256, KC=64, no gather, M=64, 256 thr, 2-stage, f32 out ----
    {
        auto k = mma_layer<128, 256, 128, 64, 2, 2, 4, 2, false, 2>;
        constexpr int smb = 2048 + 2 * (64 * 128) + 2 * (256 * 128);  // 83968
        cudaFuncSetAttribute((const void*)k, cudaFuncAttributeMaxDynamicSharedMemorySize, smb);
        k<<<grid2, 256, smb>>>(h4, nullptr, wl, bl, out);
    }
}

// round 17
// speedup vs baseline: 3.2326x; 1.0324x over previous
#include <cuda_runtime.h>
#include <cuda_bf16.h>
#include <cuda_fp16.h>
#include <cstdint>
#include <cstddef>

static constexpr int BATCH = 32;
static constexpr int NVERT = 5023;
static constexpr int SP    = 9;

// ---------------------------------------------------------------------------
// Helpers (sm_100 base target: mma.sync + ldmatrix + cp.async only)
// ---------------------------------------------------------------------------
__device__ __forceinline__ uint32_t smem_u32(const void* p) {
    uint32_t a;
    asm("{ .reg .u64 t; cvta.to.shared.u64 t, %1; cvt.u32.u64 %0, t; }" : "=r"(a) : "l"(p));
    return a;
}
__device__ __forceinline__ void cp16(uint32_t dst, const void* src, int srcbytes) {
    asm volatile("cp.async.cg.shared.global [%0], [%1], 16, %2;"
                 :: "r"(dst), "l"(src), "r"(srcbytes));
}
__device__ __forceinline__ void cp_commit() {
    asm volatile("cp.async.commit_group;" ::: "memory");
}
__device__ __forceinline__ void cp_wait1() {
    asm volatile("cp.async.wait_group 1;" ::: "memory");
}
__device__ __forceinline__ void ldm4(uint32_t addr, uint32_t* r) {
    asm volatile("ldmatrix.sync.aligned.m8n8.x4.shared.b16 {%0,%1,%2,%3}, [%4];"
                 : "=r"(r[0]), "=r"(r[1]), "=r"(r[2]), "=r"(r[3]) : "r"(addr));
}
__device__ __forceinline__ void mma_fp16(float* d, const uint32_t* a, const uint32_t* b) {
    asm volatile("mma.sync.aligned.m16n8k16.row.col.f32.f16.f16.f32 "
                 "{%0,%1,%2,%3}, {%4,%5,%6,%7}, {%8,%9}, {%0,%1,%2,%3};"
                 : "+f"(d[0]), "+f"(d[1]), "+f"(d[2]), "+f"(d[3])
                 : "r"(a[0]), "r"(a[1]), "r"(a[2]), "r"(a[3]), "r"(b[0]), "r"(b[1]));
}

// ---------------------------------------------------------------------------
// Device global scratch — fp16 activations, fp16 weights (single plane each)
// ---------------------------------------------------------------------------
__device__ __half g_h1[(size_t)BATCH * NVERT * 32];
__device__ __half g_h2[(size_t)BATCH * NVERT * 64];
__device__ __half g_h3[(size_t)BATCH * NVERT * 128];
__device__ __half g_h4[(size_t)BATCH * NVERT * 128];

__device__ float  g_wt0[27 * 32];
__device__ __half g_w1[64 * 288];
__device__ __half g_w2[128 * 576];
__device__ __half g_w3[128 * 1152];
__device__ __half g_wl[256 * 128];

// ---------------------------------------------------------------------------
// Fused weight-prep kernel: W0 transpose + fp16 convert for W1..W3, Wl
// ---------------------------------------------------------------------------
__global__ void prep_weights(const float* W0, float* wt0,
                             const float* W1, __half* w1,
                             const float* W2, __half* w2,
                             const float* W3, __half* w3,
                             const float* Wl, __half* wl) {
    int t = blockIdx.x * blockDim.x + threadIdx.x;
    if (t < 864) {
        int k = t / 32, o = t - k * 32;
        wt0[t] = W0[o * 27 + k];
        return;
    }
    t -= 864;
    const float* W; __half* dst;
    if (t < 64 * 288)                       { W = W1; dst = w1; }
    else if ((t -= 64 * 288)  < 128 * 576)  { W = W2; dst = w2; }
    else if ((t -= 128 * 576) < 128 * 1152) { W = W3; dst = w3; }
    else if ((t -= 128 * 1152) < 256 * 128) { W = Wl; dst = wl; }
    else return;
    dst[t] = __float2half_rn(W[t]);
}

// ---------------------------------------------------------------------------
// Layer 0 (SIMT fp32, tiny): 3 -> 32, emits a single fp16 plane
// ---------------------------------------------------------------------------
__global__ void __launch_bounds__(128)
layer0_kernel(const float* __restrict__ x,
              const int*   __restrict__ sidx_g,
              const float* __restrict__ Wt,
              const float* __restrict__ bias,
              __half* __restrict__ hout) {
    constexpr int IN_C = 3, OUT_C = 32, KC = 27, ROWS = 128, TM = 8, TN = 4;
    constexpr int TX = OUT_C / TN;
    constexpr int NT = 128;
    constexpr int AS = KC + 1;

    extern __shared__ __align__(1024) char dsm[];
    float* Asm = (float*)dsm;
    float* Wsm = Asm + ROWS * AS;
    int*   sidx = (int*)(Wsm + KC * OUT_C);

    const int tid = threadIdx.x;
    const int tx = tid % TX, ty = tid / TX;
    const int v0 = blockIdx.x * 4;

    if (tid < 36) {
        int vt = tid / SP, s = tid - vt * SP;
        int v = v0 + vt; if (v >= NVERT) v = NVERT - 1;
        sidx[tid] = sidx_g[v * SP + s];
    }
    for (int t = tid; t < KC * OUT_C; t += NT) Wsm[t] = Wt[t];
    __syncthreads();
    for (int t = tid; t < ROWS * KC; t += NT) {
        int r = t / KC, kk = t - r * KC;
        int vt = r >> 5, b = r & 31;
        int s = kk / IN_C, c = kk - s * IN_C;
        int srow = sidx[vt * SP + s];
        Asm[r * AS + kk] = x[((size_t)b * NVERT + srow) * IN_C + c];
    }
    __syncthreads();

    float acc[TM][TN];
#pragma unroll
    for (int i = 0; i < TM; ++i)
#pragma unroll
        for (int j = 0; j < TN; ++j) acc[i][j] = 0.f;

#pragma unroll
    for (int k = 0; k < KC; ++k) {
        float a[TM];
#pragma unroll
        for (int i = 0; i < TM; ++i) a[i] = Asm[(ty * TM + i) * AS + k];
        float4 wv = *(const float4*)(Wsm + k * OUT_C + tx * TN);
        float w[TN] = {wv.x, wv.y, wv.z, wv.w};
#pragma unroll
        for (int i = 0; i < TM; ++i)
#pragma unroll
            for (int j = 0; j < TN; ++j) acc[i][j] += a[i] * w[j];
    }

#pragma unroll
    for (int i = 0; i < TM; ++i) {
        int r = ty * TM + i;
        int vt = r >> 5, b = r & 31;
        int v = v0 + vt;
        if (v < NVERT) {
            size_t off = ((size_t)b * NVERT + v) * OUT_C + tx * TN;
#pragma unroll
            for (int j = 0; j < TN; ++j) {
                float y = acc[i][j] + __ldg(&bias[tx * TN + j]);
                hout[off + j] = __float2half_rn(y);
            }
        }
    }
}

// ---------------------------------------------------------------------------
// HMMA fp16 single-pass layer, K-chunk KC (32 or 64), 3-stage pipeline with
// ONE __syncthreads per chunk:
//   [prefetch ch+1 -> stage (ch+1)%3; cp.wait_group 1; sync; compute ch%3]
// Stage-reuse safety: prefetch target's last compute was chunk ch-2, which
// every warp finished before the sync inside iteration ch-1.
//   KC=32: 64B smem rows, SW64.  KC=64: 128B rows, SW128.
//   OUTMODE: 1 = fp16 single plane, 2 = f32 final.
// MINB = min blocks/SM for launch_bounds (controls the reg cap).
// smem header: [0,256) sidx, [256,1280) bias, [2048...) tiles.
// ---------------------------------------------------------------------------
template<int IN_C, int OUT_C, int KPAD, int KC, int MV, int WRG, int WCG,
         int MINB, bool GATHER, int OUTMODE>
__global__ void __launch_bounds__(32 * WRG * WCG, MINB)
mma_layer(const __half* __restrict__ hin,
          const int*    __restrict__ sidx_g,
          const __half* __restrict__ w,
          const float*  __restrict__ bias,
          void*         __restrict__ outp) {
    constexpr int NT    = 32 * WRG * WCG;
    constexpr int MROWS = MV * 32;
    constexpr int NCH   = KPAD / KC;
    constexpr int ROWB  = KC * 2;               // smem row bytes (64 or 128)
    constexpr int UNITS = ROWB / 16;            // 16B units per row
    constexpr uint32_t SWM = (ROWB == 64) ? 0x30u : 0x70u;
    constexpr int ATB   = MROWS * ROWB;         // bytes per A stage
    constexpr int BTB   = OUT_C * ROWB;         // bytes per B stage
    constexpr int SM_A  = 2048;
    constexpr int SM_B  = SM_A + 3 * ATB;
    constexpr int WARP_R = MROWS / WRG;
    constexpr int WARP_C = OUT_C / WCG;
    constexpr int RS = WARP_R / 16;
    constexpr int NO = WARP_C / 8;
    constexpr int KS = KC / 16;                 // k16 steps per chunk
    constexpr int TOT_A = MROWS * UNITS;
    constexpr int TOT_B = OUT_C * UNITS;

    extern __shared__ __align__(1024) char dsm[];
    const uint32_t sbase = smem_u32(dsm);
    int*   sidx = (int*)dsm;
    float* bsm  = (float*)(dsm + 256);

    const int tid  = threadIdx.x;
    const int wid  = tid >> 5;
    const int lane = tid & 31;
    const int v0   = blockIdx.x * MV;

    const int wr = wid % WRG, wc = wid / WRG;
    const int warp_r0 = wr * WARP_R;
    const int warp_c0 = wc * WARP_C;

    auto swz = [](uint32_t off) { return off ^ ((off >> 3) & SWM); };

    if (GATHER && tid < MV * SP) {
        int vt = tid / SP, s = tid - vt * SP;
        int v = v0 + vt; if (v >= NVERT) v = NVERT - 1;
        sidx[tid] = sidx_g[v * SP + s];
    }
    for (int t = tid; t < OUT_C; t += NT) bsm[t] = bias[t];
    __syncthreads();

    // ---- chunk loader into pipeline stage st ----
    auto load_chunk = [&](int ch, int st) {
#pragma unroll
        for (int t = tid; t < TOT_A; t += NT) {
            int r = t / UNITS, g = t % UNITS;
            int vt = r >> 5, b = r & 31;
            int kg = ch * KC + g * 8;
            int s = GATHER ? kg / IN_C : 0;
            int c = GATHER ? kg - s * IN_C : kg;
            int v = v0 + vt; if (v >= NVERT) v = NVERT - 1;
            int srow = GATHER ? sidx[vt * SP + s] : v;
            const __half* src = hin + ((size_t)b * NVERT + srow) * IN_C + c;
            uint32_t dst = sbase + SM_A + (uint32_t)st * ATB
                         + swz((uint32_t)(r * ROWB + g * 16));
            cp16(dst, src, 16);
        }
#pragma unroll
        for (int t = tid; t < TOT_B; t += NT) {
            int n = t / UNITS, g = t % UNITS;
            int kg = ch * KC + g * 8;
            const __half* src = w + (size_t)n * KPAD + kg;
            uint32_t dst = sbase + SM_B + (uint32_t)st * BTB
                         + swz((uint32_t)(n * ROWB + g * 16));
            cp16(dst, src, 16);
        }
        cp_commit();
    };

    float acc[RS][NO][4];
#pragma unroll
    for (int i = 0; i < RS; ++i)
#pragma unroll
        for (int j = 0; j < NO; ++j)
#pragma unroll
            for (int q = 0; q < 4; ++q) acc[i][j][q] = 0.f;

    const int grp = lane >> 3, lr = lane & 7;

    load_chunk(0, 0);

    for (int ch = 0; ch < NCH; ++ch) {
        const int st = ch % 3;

        // prefetch next chunk (issued before the wait; target stage's last
        // compute was chunk ch-2, finished by all warps before the sync in
        // iteration ch-1)
        if (ch + 1 < NCH) load_chunk(ch + 1, (ch + 1) % 3);
        else              cp_commit();     // keep group accounting aligned

        cp_wait1();        // chunk ch complete (only ch+1 may be pending)
        __syncthreads();   // all warps' copies of chunk ch visible

        const uint32_t A_ = sbase + SM_A + (uint32_t)st * ATB;
        const uint32_t B_ = sbase + SM_B + (uint32_t)st * BTB;

#pragma unroll
        for (int ks = 0; ks < KS; ++ks) {
            uint32_t bf[NO][2];
#pragma unroll
            for (int p16 = 0; p16 < NO / 2; ++p16) {
                int n  = warp_c0 + p16 * 16 + (grp >> 1) * 8 + lr;
                int c16 = ks * 2 + (grp & 1);
                uint32_t off = swz((uint32_t)(n * ROWB + c16 * 16));
                uint32_t m[4];
                ldm4(B_ + off, m);
                bf[2 * p16][0] = m[0]; bf[2 * p16][1] = m[1];
                bf[2 * p16 + 1][0] = m[2]; bf[2 * p16 + 1][1] = m[3];
            }
#pragma unroll
            for (int sub = 0; sub < RS; ++sub) {
                int row = warp_r0 + sub * 16 + (grp & 1) * 8 + lr;
                int c16 = ks * 2 + (grp >> 1);
                uint32_t off = swz((uint32_t)(row * ROWB + c16 * 16));
                uint32_t ah[4];
                ldm4(A_ + off, ah);
#pragma unroll
                for (int oct = 0; oct < NO; ++oct)
                    mma_fp16(acc[sub][oct], ah, bf[oct]);
            }
        }
        // no trailing barrier: 3-stage ring guarantees the stage refilled at
        // iteration ch+1 is the one last computed at chunk ch-1, and the sync
        // above already ordered that compute for every warp.
    }

    // ---- epilogue: bias + store per OUTMODE ----
    const int tq = lane >> 2, tr = lane & 3;
#pragma unroll
    for (int sub = 0; sub < RS; ++sub) {
#pragma unroll
        for (int half = 0; half < 2; ++half) {
            int r = warp_r0 + sub * 16 + half * 8 + tq;
            int vt = r >> 5, b = r & 31;
            int v = v0 + vt;
            if (v >= NVERT) continue;
#pragma unroll
            for (int oct = 0; oct < NO; ++oct) {
                int col = warp_c0 + oct * 8 + tr * 2;
                float y0 = acc[sub][oct][2 * half]     + bsm[col];
                float y1 = acc[sub][oct][2 * half + 1] + bsm[col + 1];
                size_t base = ((size_t)b * NVERT + v) * OUT_C + col;
                if constexpr (OUTMODE == 2) {
                    *(float2*)((float*)outp + base) = make_float2(y0, y1);
                } else {
                    __half2 hp = __floats2half2_rn(y0, y1);
                    *(uint32_t*)((__half*)outp + base) = *reinterpret_cast<uint32_t*>(&hp);
                }
            }
        }
    }
}

// ---------------------------------------------------------------------------
// Host
// ---------------------------------------------------------------------------
extern "C" void kernel_launch(void* const* d_in, const int* in_sizes, int n_in,
                              void* d_out, int out_size) {
    const float* x  = (const float*)d_in[0];
    const int*   sp = (const int*)  d_in[1];
    const float* W0 = (const float*)d_in[2];
    const float* b0 = (const float*)d_in[3];
    const float* W1 = (const float*)d_in[4];
    const float* b1 = (const float*)d_in[5];
    const float* W2 = (const float*)d_in[6];
    const float* b2 = (const float*)d_in[7];
    const float* W3 = (const float*)d_in[8];
    const float* b3 = (const float*)d_in[9];
    const float* Wl = (const float*)d_in[10];
    const float* bl = (const float*)d_in[11];
    float* out = (float*)d_out;

    __half *h1, *h2, *h3, *h4, *w1, *w2, *w3, *wl;
    float *wt0;
    cudaGetSymbolAddress((void**)&h1, g_h1);
    cudaGetSymbolAddress((void**)&h2, g_h2);
    cudaGetSymbolAddress((void**)&h3, g_h3);
    cudaGetSymbolAddress((void**)&h4, g_h4);
    cudaGetSymbolAddress((void**)&w1, g_w1);
    cudaGetSymbolAddress((void**)&w2, g_w2);
    cudaGetSymbolAddress((void**)&w3, g_w3);
    cudaGetSymbolAddress((void**)&wl, g_wl);
    cudaGetSymbolAddress((void**)&wt0, g_wt0);

    // ---- fused weight prep (1 launch) ----
    {
        const int total = 864 + 64 * 288 + 128 * 576 + 128 * 1152 + 256 * 128;
        prep_weights<<<(total + 255) / 256, 256>>>(W0, wt0, W1, w1, W2, w2,
                                                   W3, w3, Wl, wl);
    }

    const int* sp0 = sp + 0 * NVERT * SP;
    const int* sp1 = sp + 1 * NVERT * SP;
    const int* sp2 = sp + 2 * NVERT * SP;
    const int* sp3 = sp + 3 * NVERT * SP;

    const int grid4 = (NVERT + 3) / 4;   // 1256
    const int grid2 = (NVERT + 1) / 2;   // 2512

    // ---- Layer 0 (SIMT, fp32 math, fp16 out) ----
    {
        constexpr int smb = (128 * 28 + 27 * 32) * 4 + 64 * 4;
        layer0_kernel<<<grid4, 128, smb>>>(x, sp0, wt0, b0, h1);
    }
    // ---- Layer 1: 32 -> 64, K=288, KC=32, M=128, 256 thr, 2 CTA/SM ----
    {
        auto k = mma_layer<32, 64, 288, 32, 4, 4, 2, 2, true, 1>;
        constexpr int smb = 2048 + 3 * (128 * 64) + 3 * (64 * 64);    // 38912
        cudaFuncSetAttribute((const void*)k, cudaFuncAttributeMaxDynamicSharedMemorySize, smb);
        k<<<grid4, 256, smb>>>(h1, sp1, w1, b1, h2);
    }
    // ---- Layer 2: 64 -> 128, K=576, KC=64, M=64, 128 thr, 3 CTA/SM ----
    {
        auto k = mma_layer<64, 128, 576, 64, 2, 1, 4, 3, true, 1>;
        constexpr int smb = 2048 + 3 * (64 * 128) + 3 * (128 * 128);  // 75776
        cudaFuncSetAttribute((const void*)k, cudaFuncAttributeMaxDynamicSharedMemorySize, smb);
        k<<<grid2, 128, smb>>>(h2, sp2, w2, b2, h3);
    }
    // ---- Layer 3: 128 -> 128, K=1152, KC=64, M=64, 128 thr, 3 CTA/SM ----
    {
        auto k = mma_layer<128, 128, 1152, 64, 2, 1, 4, 3, true, 1>;
        constexpr int smb = 2048 + 3 * (64 * 128) + 3 * (128 * 128);  // 75776
        cudaFuncSetAttribute((const void*)k, cudaFuncAttributeMaxDynamicSharedMemorySize, smb);
        k<<<grid2, 128, smb>>>(h3, sp3, w3, b3, h4);
    }
    // ---- Final: 128 -> 256, KC=32, no gather, M=64, 256 thr, 2 CTA/SM ----
    {
        auto k = mma_layer<128, 256, 128, 32, 2, 2, 4, 2, false, 2>;
        constexpr int smb = 2048 + 3 * (64 * 64) + 3 * (256 * 64);    // 63488
        cudaFuncSetAttribute((const void*)k, cudaFuncAttributeMaxDynamicSharedMemorySize, smb);
        k<<<grid2, 256, smb>>>(h4, nullptr, wl, bl, out);
    }
}